// round 3
// baseline (speedup 1.0000x reference)
#include <cuda_runtime.h>
#include <math.h>

#define B_  2
#define T_  2048
#define E_  1024
#define H_  16
#define HS_ 64
#define BT  (B_*T_)     // 4096 rows
#define FF  (4*E_)      // 4096

// ---------------- scratch (no allocations allowed; __device__ globals) ------
__device__ float g_h   [BT * E_];        // LN1 output
__device__ float g_wqkv[E_ * 3 * E_];    // repacked QKV weights [E, 3E]
__device__ float g_qkv [BT * 3 * E_];    // Q|K|V per row
__device__ float g_attn[BT * E_];        // attention out (concat heads)
__device__ float g_x1  [BT * E_];        // residual 1
__device__ float g_h2  [BT * E_];        // LN2 output
__device__ float g_ff1 [BT * FF];        // FFN hidden

// ---------------- LayerNorm: one block per row ------------------------------
__global__ __launch_bounds__(256) void ln_kernel(const float* __restrict__ x,
                                                 const float* __restrict__ g,
                                                 const float* __restrict__ b,
                                                 float* __restrict__ out)
{
    int row = blockIdx.x;
    int tid = threadIdx.x;
    const float4* xr = reinterpret_cast<const float4*>(x + (size_t)row * E_);
    float4 v = xr[tid];
    float s  = v.x + v.y + v.z + v.w;
    float sq = v.x*v.x + v.y*v.y + v.z*v.z + v.w*v.w;

    __shared__ float sh[16];
    __shared__ float s_mu, s_rs;
    #pragma unroll
    for (int o = 16; o > 0; o >>= 1) {
        s  += __shfl_down_sync(0xffffffffu, s,  o);
        sq += __shfl_down_sync(0xffffffffu, sq, o);
    }
    int lane = tid & 31, wid = tid >> 5;
    if (lane == 0) { sh[wid] = s; sh[8 + wid] = sq; }
    __syncthreads();
    if (tid == 0) {
        float ts = 0.f, tq = 0.f;
        #pragma unroll
        for (int w = 0; w < 8; w++) { ts += sh[w]; tq += sh[8 + w]; }
        float mu  = ts * (1.0f / E_);
        float var = tq * (1.0f / E_) - mu * mu;
        s_mu = mu;
        s_rs = rsqrtf(var + 1e-5f);
    }
    __syncthreads();
    float mu = s_mu, rs = s_rs;
    float4 gg = reinterpret_cast<const float4*>(g)[tid];
    float4 bb = reinterpret_cast<const float4*>(b)[tid];
    float4 r;
    r.x = (v.x - mu) * rs * gg.x + bb.x;
    r.y = (v.y - mu) * rs * gg.y + bb.y;
    r.z = (v.z - mu) * rs * gg.z + bb.z;
    r.w = (v.w - mu) * rs * gg.w + bb.w;
    reinterpret_cast<float4*>(out + (size_t)row * E_)[tid] = r;
}

// ---------------- Repack Wq/Wk/Wv [H,E,HS] -> [E, 3E] -----------------------
__global__ void repack_kernel(const float* __restrict__ Wq,
                              const float* __restrict__ Wk,
                              const float* __restrict__ Wv,
                              float* __restrict__ Wqkv)
{
    int i = blockIdx.x * blockDim.x + threadIdx.x;   // over H*E*HS = 1M
    if (i >= H_ * E_ * HS_) return;
    int h = i / (E_ * HS_);
    int r = i % (E_ * HS_);
    int e = r / HS_;
    int d = r % HS_;
    int col = h * HS_ + d;
    size_t base = (size_t)e * (3 * E_);
    Wqkv[base + col]           = Wq[i];
    Wqkv[base + E_ + col]      = Wk[i];
    Wqkv[base + 2 * E_ + col]  = Wv[i];
}

// ---------------- SGEMM 128x128x8, 256 threads, 8x8 micro-tile --------------
// C[M,N] = A[M,K] @ B[K,N]  (+bias per col, optional ReLU, optional +res[M,N])
__global__ __launch_bounds__(256) void sgemm_kernel(
    const float* __restrict__ A, const float* __restrict__ Bm,
    float* __restrict__ C, int M, int N, int K,
    const float* __restrict__ bias, const float* __restrict__ res, int relu)
{
    const int BM = 128, BN = 128, BK = 8;
    __shared__ float As[BK][BM];
    __shared__ float Bs[BK][BN];

    int tid = threadIdx.x;
    int tx = tid & 15, ty = tid >> 4;
    int m0 = blockIdx.y * BM, n0 = blockIdx.x * BN;

    // A tile load: one float4 per thread. row=tid/2 (0..127), col=(tid&1)*4
    int a_r = tid >> 1, a_c = (tid & 1) * 4;
    // B tile load: row=tid/32 (0..7), col=(tid&31)*4
    int b_r = tid >> 5, b_c = (tid & 31) * 4;

    const float* Aptr = A  + (size_t)(m0 + a_r) * K + a_c;
    const float* Bptr = Bm + (size_t)b_r * N + n0 + b_c;

    float acc[8][8];
    #pragma unroll
    for (int i = 0; i < 8; i++)
        #pragma unroll
        for (int j = 0; j < 8; j++) acc[i][j] = 0.f;

    for (int k0 = 0; k0 < K; k0 += BK) {
        float4 av = *reinterpret_cast<const float4*>(Aptr + k0);
        float4 bv = *reinterpret_cast<const float4*>(Bptr + (size_t)k0 * N);
        As[a_c + 0][a_r] = av.x;
        As[a_c + 1][a_r] = av.y;
        As[a_c + 2][a_r] = av.z;
        As[a_c + 3][a_r] = av.w;
        *reinterpret_cast<float4*>(&Bs[b_r][b_c]) = bv;
        __syncthreads();

        #pragma unroll
        for (int kk = 0; kk < BK; kk++) {
            float a[8], bb[8];
            #pragma unroll
            for (int i = 0; i < 8; i++) a[i]  = As[kk][ty * 8 + i];
            #pragma unroll
            for (int j = 0; j < 8; j++) bb[j] = Bs[kk][tx * 8 + j];
            #pragma unroll
            for (int i = 0; i < 8; i++)
                #pragma unroll
                for (int j = 0; j < 8; j++)
                    acc[i][j] += a[i] * bb[j];
        }
        __syncthreads();
    }

    #pragma unroll
    for (int i = 0; i < 8; i++) {
        int row = m0 + ty * 8 + i;
        #pragma unroll
        for (int j = 0; j < 8; j++) {
            int col = n0 + tx * 8 + j;
            float v = acc[i][j];
            if (bias) v += bias[col];
            if (relu) v = fmaxf(v, 0.f);
            if (res)  v += res[(size_t)row * N + col];
            C[(size_t)row * N + col] = v;
        }
    }
}

// ---------------- Causal flash attention ------------------------------------
// grid (T/64, B*H), 64 threads/block. Each thread owns one query row:
// Q (scaled) and O accumulator in registers; K/V 64x64 tiles in SMEM;
// online softmax with per-tile rescale; score tile in swizzled SMEM.
__global__ __launch_bounds__(64) void attn_kernel(const float* __restrict__ qkv,
                                                  float* __restrict__ out)
{
    __shared__ float Ks[64 * 64];
    __shared__ float Vs[64 * 64];
    __shared__ float Ss[64 * 64];

    int tid = threadIdx.x;
    int qt  = blockIdx.x;
    int bh  = blockIdx.y;
    int b = bh >> 4, h = bh & 15;
    int qi = qt * 64 + tid;
    const float scale = 0.125f;  // HS^-0.5 = 1/8

    float q[64], o[64];
    const float* qrow = qkv + (size_t)(b * T_ + qi) * (3 * E_) + h * HS_;
    #pragma unroll
    for (int k = 0; k < 64; k++) q[k] = qrow[k] * scale;
    #pragma unroll
    for (int k = 0; k < 64; k++) o[k] = 0.f;
    float m = -1e30f, l = 0.f;

    int sw = tid & 31;  // score-tile bank swizzle

    for (int kt = 0; kt <= qt; kt++) {
        const float* kbase = qkv + (size_t)(b * T_ + kt * 64) * (3 * E_) + E_ + h * HS_;
        const float* vbase = kbase + E_;
        for (int r = 0; r < 64; r++) {
            Ks[r * 64 + tid] = kbase[(size_t)r * (3 * E_) + tid];
            Vs[r * 64 + tid] = vbase[(size_t)r * (3 * E_) + tid];
        }
        __syncthreads();

        int jmax = (kt == qt) ? (tid + 1) : 64;  // causal: key <= query
        float mt = -1e30f;
        for (int j = 0; j < jmax; j++) {
            float s = 0.f;
            #pragma unroll
            for (int k = 0; k < 64; k++) s += q[k] * Ks[j * 64 + k];
            Ss[tid * 64 + (j ^ sw)] = s;
            mt = fmaxf(mt, s);
        }
        float mn = fmaxf(m, mt);
        float corr = __expf(m - mn);
        #pragma unroll
        for (int k = 0; k < 64; k++) o[k] *= corr;
        l *= corr;
        m = mn;
        for (int j = 0; j < jmax; j++) {
            float p = __expf(Ss[tid * 64 + (j ^ sw)] - m);
            l += p;
            #pragma unroll
            for (int k = 0; k < 64; k++) o[k] += p * Vs[j * 64 + k];
        }
        __syncthreads();
    }

    float inv = 1.f / l;
    float* orow = out + (size_t)(b * T_ + qi) * E_ + h * HS_;
    #pragma unroll
    for (int k = 0; k < 64; k++) orow[k] = o[k] * inv;
}

// ---------------- host ------------------------------------------------------
extern "C" void kernel_launch(void* const* d_in, const int* in_sizes, int n_in,
                              void* d_out, int out_size)
{
    const float* x   = (const float*)d_in[0];
    const float* Wq  = (const float*)d_in[1];
    const float* Wk  = (const float*)d_in[2];
    const float* Wv  = (const float*)d_in[3];
    const float* Wp  = (const float*)d_in[4];
    const float* bp  = (const float*)d_in[5];
    const float* W1  = (const float*)d_in[6];
    const float* b1  = (const float*)d_in[7];
    const float* W2  = (const float*)d_in[8];
    const float* b2  = (const float*)d_in[9];
    const float* g1  = (const float*)d_in[10];
    const float* be1 = (const float*)d_in[11];
    const float* g2  = (const float*)d_in[12];
    const float* be2 = (const float*)d_in[13];
    float* out = (float*)d_out;

    float *h, *wqkv, *qkv, *attn, *x1, *h2, *ff1;
    cudaGetSymbolAddress((void**)&h,    g_h);
    cudaGetSymbolAddress((void**)&wqkv, g_wqkv);
    cudaGetSymbolAddress((void**)&qkv,  g_qkv);
    cudaGetSymbolAddress((void**)&attn, g_attn);
    cudaGetSymbolAddress((void**)&x1,   g_x1);
    cudaGetSymbolAddress((void**)&h2,   g_h2);
    cudaGetSymbolAddress((void**)&ff1,  g_ff1);

    // 1) h = LN1(x)
    ln_kernel<<<BT, 256>>>(x, g1, be1, h);
    // 2) repack QKV weights
    repack_kernel<<<(H_ * E_ * HS_ + 255) / 256, 256>>>(Wq, Wk, Wv, wqkv);
    // 3) QKV = h @ Wqkv          [4096,1024] x [1024,3072]
    sgemm_kernel<<<dim3(3 * E_ / 128, BT / 128), 256>>>(
        h, wqkv, qkv, BT, 3 * E_, E_, nullptr, nullptr, 0);
    // 4) causal attention
    attn_kernel<<<dim3(T_ / 64, B_ * H_), 64>>>(qkv, attn);
    // 5) x1 = x + attn @ Wp + bp [4096,1024] x [1024,1024]
    sgemm_kernel<<<dim3(E_ / 128, BT / 128), 256>>>(
        attn, Wp, x1, BT, E_, E_, bp, x, 0);
    // 6) h2 = LN2(x1)
    ln_kernel<<<BT, 256>>>(x1, g2, be2, h2);
    // 7) ff1 = relu(h2 @ W1 + b1) [4096,1024] x [1024,4096]
    sgemm_kernel<<<dim3(FF / 128, BT / 128), 256>>>(
        h2, W1, ff1, BT, FF, E_, b1, nullptr, 1);
    // 8) out = x1 + ff1 @ W2 + b2 [4096,4096] x [4096,1024]
    sgemm_kernel<<<dim3(E_ / 128, BT / 128), 256>>>(
        ff1, W2, out, BT, E_, FF, b2, x1, 0);
}

// round 6
// speedup vs baseline: 1.3569x; 1.3569x over previous
#include <cuda_runtime.h>
#include <math.h>
#include <stdint.h>
#include <mma.h>

using namespace nvcuda;

#define B_  2
#define T_  2048
#define E_  1024
#define H_  16
#define HS_ 64
#define NROWS (B_*T_)   // 4096 rows
#define FF  (4*E_)      // 4096

// ---------------- scratch ----------------------------------------------------
__device__ float g_h   [NROWS * E_];     // LN1 output
__device__ float g_wqkv[E_ * 3 * E_];    // repacked QKV weights [E, 3E]
__device__ float g_qkv [NROWS * 3 * E_]; // Q|K|V per row
__device__ float g_attn[NROWS * E_];     // attention out
__device__ float g_x1  [NROWS * E_];     // residual 1
__device__ float g_h2  [NROWS * E_];     // LN2 output
__device__ float g_ff1 [NROWS * FF];     // FFN hidden

// ---------------- LayerNorm --------------------------------------------------
__global__ __launch_bounds__(256) void ln_kernel(const float* __restrict__ x,
                                                 const float* __restrict__ g,
                                                 const float* __restrict__ b,
                                                 float* __restrict__ out)
{
    int row = blockIdx.x;
    int tid = threadIdx.x;
    const float4* xr = reinterpret_cast<const float4*>(x + (size_t)row * E_);
    float4 v = xr[tid];
    float s  = v.x + v.y + v.z + v.w;
    float sq = v.x*v.x + v.y*v.y + v.z*v.z + v.w*v.w;

    __shared__ float sh[16];
    __shared__ float s_mu, s_rs;
    #pragma unroll
    for (int o = 16; o > 0; o >>= 1) {
        s  += __shfl_down_sync(0xffffffffu, s,  o);
        sq += __shfl_down_sync(0xffffffffu, sq, o);
    }
    int lane = tid & 31, wid = tid >> 5;
    if (lane == 0) { sh[wid] = s; sh[8 + wid] = sq; }
    __syncthreads();
    if (tid == 0) {
        float ts = 0.f, tq = 0.f;
        #pragma unroll
        for (int w = 0; w < 8; w++) { ts += sh[w]; tq += sh[8 + w]; }
        float mu  = ts * (1.0f / E_);
        float var = tq * (1.0f / E_) - mu * mu;
        s_mu = mu;
        s_rs = rsqrtf(var + 1e-5f);
    }
    __syncthreads();
    float mu = s_mu, rs = s_rs;
    float4 gg = reinterpret_cast<const float4*>(g)[tid];
    float4 bb = reinterpret_cast<const float4*>(b)[tid];
    float4 r;
    r.x = (v.x - mu) * rs * gg.x + bb.x;
    r.y = (v.y - mu) * rs * gg.y + bb.y;
    r.z = (v.z - mu) * rs * gg.z + bb.z;
    r.w = (v.w - mu) * rs * gg.w + bb.w;
    reinterpret_cast<float4*>(out + (size_t)row * E_)[tid] = r;
}

// ---------------- Repack Wq/Wk/Wv [H,E,HS] -> [E, 3E] ------------------------
__global__ void repack_kernel(const float* __restrict__ Wq,
                              const float* __restrict__ Wk,
                              const float* __restrict__ Wv,
                              float* __restrict__ Wqkv)
{
    int i = blockIdx.x * blockDim.x + threadIdx.x;   // over H*E*HS = 1M
    if (i >= H_ * E_ * HS_) return;
    int h = i / (E_ * HS_);
    int r = i % (E_ * HS_);
    int e = r / HS_;
    int d = r % HS_;
    int col = h * HS_ + d;
    size_t base = (size_t)e * (3 * E_);
    Wqkv[base + col]           = Wq[i];
    Wqkv[base + E_ + col]      = Wk[i];
    Wqkv[base + 2 * E_ + col]  = Wv[i];
}

// ---------------- WMMA TF32 GEMM --------------------------------------------
// C[M,N] = A[M,K] @ Bm[K,N]   (+bias per col, optional ReLU, optional +res)
// Tile 128x128, BK=32, 256 threads (8 warps, each 64x32).
#define BM   128
#define BN   128
#define BKC  32
#define AST  36                    // A smem row stride (floats)
#define BST  132                   // B smem row stride (floats)
#define STAGE_F (BM*AST + BKC*BST) // 4608 + 4224 = 8832 floats / stage
#define GSMEM (2 * STAGE_F * 4)    // 70656 bytes

__device__ __forceinline__ void cp_async16(uint32_t dst, const void* src) {
    asm volatile("cp.async.cg.shared.global [%0], [%1], 16;" :: "r"(dst), "l"(src));
}

__global__ __launch_bounds__(256) void tf32_gemm(
    const float* __restrict__ A, const float* __restrict__ Bm,
    float* __restrict__ C, int M, int N, int K,
    const float* __restrict__ bias, const float* __restrict__ res, int relu)
{
    extern __shared__ float sm[];
    uint32_t sm_u32;
    asm("{ .reg .u64 t; cvta.to.shared.u64 t, %1; cvt.u32.u64 %0, t; }"
        : "=r"(sm_u32) : "l"(sm));

    int tid  = threadIdx.x;
    int wid  = tid >> 5;
    int wm   = wid & 1;        // 0..1  -> 64-row slab
    int wn   = wid >> 1;       // 0..3  -> 32-col slab
    int m0   = blockIdx.y * BM;
    int n0   = blockIdx.x * BN;
    int NC   = K / BKC;

    // per-thread load coordinates
    int a_row = tid >> 1;            // 0..127
    int a_kk  = (tid & 1) * 16;      // 0 or 16 -> covers 32 with 2 iters? no:
    // A tile: 128 rows x 32 floats = 128 rows x 2 x 16B -> 256 ops, 1 per thread... 
    // Actually: 128*32*4 = 16KB = 1024 x 16B. 4 per thread.
    // Use idx mapping instead.

    wmma::fragment<wmma::accumulator, 16, 16, 8, float> acc[4][2];
    #pragma unroll
    for (int i = 0; i < 4; i++)
        #pragma unroll
        for (int j = 0; j < 2; j++)
            wmma::fill_fragment(acc[i][j], 0.0f);

    // ---- async tile loader ----
    auto issue = [&](int c, int buf) {
        uint32_t stA = sm_u32 + (uint32_t)(buf * STAGE_F) * 4u;
        uint32_t stB = stA + (uint32_t)(BM * AST) * 4u;
        int k0 = c * BKC;
        // A: 1024 x 16B
        #pragma unroll
        for (int t = 0; t < 4; t++) {
            int idx = tid + t * 256;
            int r  = idx >> 3;            // 0..127
            int kk = (idx & 7) * 4;       // 0..28
            cp_async16(stA + (uint32_t)(r * AST + kk) * 4u,
                       A + (size_t)(m0 + r) * K + k0 + kk);
        }
        // B: 1024 x 16B
        #pragma unroll
        for (int t = 0; t < 4; t++) {
            int idx = tid + t * 256;
            int r  = idx >> 5;            // 0..31
            int nn = (idx & 31) * 4;      // 0..124
            cp_async16(stB + (uint32_t)(r * BST + nn) * 4u,
                       Bm + (size_t)(k0 + r) * N + n0 + nn);
        }
        asm volatile("cp.async.commit_group;" ::: "memory");
    };

    issue(0, 0);

    for (int c = 0; c < NC; c++) {
        int buf = c & 1;
        if (c + 1 < NC) issue(c + 1, buf ^ 1);
        if (c + 1 < NC) { asm volatile("cp.async.wait_group 1;" ::: "memory"); }
        else            { asm volatile("cp.async.wait_group 0;" ::: "memory"); }
        __syncthreads();

        const float* sA = sm + buf * STAGE_F;
        const float* sB = sA + BM * AST;

        #pragma unroll
        for (int kk = 0; kk < 4; kk++) {
            wmma::fragment<wmma::matrix_a, 16, 16, 8, wmma::precision::tf32, wmma::row_major> af[4];
            wmma::fragment<wmma::matrix_b, 16, 16, 8, wmma::precision::tf32, wmma::row_major> bf[2];
            #pragma unroll
            for (int i = 0; i < 4; i++) {
                wmma::load_matrix_sync(af[i], sA + (wm * 64 + i * 16) * AST + kk * 8, AST);
                #pragma unroll
                for (int t = 0; t < af[i].num_elements; t++)
                    af[i].x[t] = wmma::__float_to_tf32(af[i].x[t]);
            }
            #pragma unroll
            for (int j = 0; j < 2; j++) {
                wmma::load_matrix_sync(bf[j], sB + (kk * 8) * BST + wn * 32 + j * 16, BST);
                #pragma unroll
                for (int t = 0; t < bf[j].num_elements; t++)
                    bf[j].x[t] = wmma::__float_to_tf32(bf[j].x[t]);
            }
            #pragma unroll
            for (int i = 0; i < 4; i++)
                #pragma unroll
                for (int j = 0; j < 2; j++)
                    wmma::mma_sync(acc[i][j], af[i], bf[j], acc[i][j]);
        }
        __syncthreads();
    }

    // ---- epilogue: fragments -> smem staging -> global with bias/relu/res ----
    float* Cs = sm;   // reuse (128 x BST staging = 67584 B <= GSMEM)
    #pragma unroll
    for (int i = 0; i < 4; i++)
        #pragma unroll
        for (int j = 0; j < 2; j++)
            wmma::store_matrix_sync(Cs + (wm * 64 + i * 16) * BST + wn * 32 + j * 16,
                                    acc[i][j], BST, wmma::mem_row_major);
    __syncthreads();

    for (int idx = tid; idx < BM * BN / 4; idx += 256) {
        int r  = idx >> 5;        // 0..127
        int c4 = idx & 31;        // 0..31  (float4 col)
        float4 v = *reinterpret_cast<const float4*>(Cs + r * BST + c4 * 4);
        int col = n0 + c4 * 4;
        size_t row = (size_t)(m0 + r);
        if (bias) {
            float4 bb = *reinterpret_cast<const float4*>(bias + col);
            v.x += bb.x; v.y += bb.y; v.z += bb.z; v.w += bb.w;
        }
        if (relu) {
            v.x = fmaxf(v.x, 0.f); v.y = fmaxf(v.y, 0.f);
            v.z = fmaxf(v.z, 0.f); v.w = fmaxf(v.w, 0.f);
        }
        if (res) {
            float4 rr = *reinterpret_cast<const float4*>(res + row * N + col);
            v.x += rr.x; v.y += rr.y; v.z += rr.z; v.w += rr.w;
        }
        *reinterpret_cast<float4*>(C + row * N + col) = v;
    }
}

// ---------------- Causal flash attention (unchanged, known-good) -------------
__global__ __launch_bounds__(64) void attn_kernel(const float* __restrict__ qkv,
                                                  float* __restrict__ out)
{
    __shared__ float Ks[64 * 64];
    __shared__ float Vs[64 * 64];
    __shared__ float Ss[64 * 64];

    int tid = threadIdx.x;
    int qt  = blockIdx.x;
    int bh  = blockIdx.y;
    int b = bh >> 4, h = bh & 15;
    int qi = qt * 64 + tid;
    const float scale = 0.125f;

    float q[64], o[64];
    const float* qrow = qkv + (size_t)(b * T_ + qi) * (3 * E_) + h * HS_;
    #pragma unroll
    for (int k = 0; k < 64; k++) q[k] = qrow[k] * scale;
    #pragma unroll
    for (int k = 0; k < 64; k++) o[k] = 0.f;
    float m = -1e30f, l = 0.f;

    int sw = tid & 31;

    for (int kt = 0; kt <= qt; kt++) {
        const float* kbase = qkv + (size_t)(b * T_ + kt * 64) * (3 * E_) + E_ + h * HS_;
        const float* vbase = kbase + E_;
        for (int r = 0; r < 64; r++) {
            Ks[r * 64 + tid] = kbase[(size_t)r * (3 * E_) + tid];
            Vs[r * 64 + tid] = vbase[(size_t)r * (3 * E_) + tid];
        }
        __syncthreads();

        int jmax = (kt == qt) ? (tid + 1) : 64;
        float mt = -1e30f;
        for (int j = 0; j < jmax; j++) {
            float s = 0.f;
            #pragma unroll
            for (int k = 0; k < 64; k++) s += q[k] * Ks[j * 64 + k];
            Ss[tid * 64 + (j ^ sw)] = s;
            mt = fmaxf(mt, s);
        }
        float mn = fmaxf(m, mt);
        float corr = __expf(m - mn);
        #pragma unroll
        for (int k = 0; k < 64; k++) o[k] *= corr;
        l *= corr;
        m = mn;
        for (int j = 0; j < jmax; j++) {
            float p = __expf(Ss[tid * 64 + (j ^ sw)] - m);
            l += p;
            #pragma unroll
            for (int k = 0; k < 64; k++) o[k] += p * Vs[j * 64 + k];
        }
        __syncthreads();
    }

    float inv = 1.f / l;
    float* orow = out + (size_t)(b * T_ + qi) * E_ + h * HS_;
    #pragma unroll
    for (int k = 0; k < 64; k++) orow[k] = o[k] * inv;
}

// ---------------- host -------------------------------------------------------
extern "C" void kernel_launch(void* const* d_in, const int* in_sizes, int n_in,
                              void* d_out, int out_size)
{
    const float* x   = (const float*)d_in[0];
    const float* Wq  = (const float*)d_in[1];
    const float* Wk  = (const float*)d_in[2];
    const float* Wv  = (const float*)d_in[3];
    const float* Wp  = (const float*)d_in[4];
    const float* bp  = (const float*)d_in[5];
    const float* W1  = (const float*)d_in[6];
    const float* b1  = (const float*)d_in[7];
    const float* W2  = (const float*)d_in[8];
    const float* b2  = (const float*)d_in[9];
    const float* g1  = (const float*)d_in[10];
    const float* be1 = (const float*)d_in[11];
    const float* g2  = (const float*)d_in[12];
    const float* be2 = (const float*)d_in[13];
    float* out = (float*)d_out;

    float *h, *wqkv, *qkv, *attn, *x1, *h2, *ff1;
    cudaGetSymbolAddress((void**)&h,    g_h);
    cudaGetSymbolAddress((void**)&wqkv, g_wqkv);
    cudaGetSymbolAddress((void**)&qkv,  g_qkv);
    cudaGetSymbolAddress((void**)&attn, g_attn);
    cudaGetSymbolAddress((void**)&x1,   g_x1);
    cudaGetSymbolAddress((void**)&h2,   g_h2);
    cudaGetSymbolAddress((void**)&ff1,  g_ff1);

    cudaFuncSetAttribute(tf32_gemm, cudaFuncAttributeMaxDynamicSharedMemorySize, GSMEM);

    // 1) h = LN1(x); repack QKV weights
    ln_kernel<<<NROWS, 256>>>(x, g1, be1, h);
    repack_kernel<<<(H_ * E_ * HS_ + 255) / 256, 256>>>(Wq, Wk, Wv, wqkv);
    // 2) QKV = h @ Wqkv        [4096,1024] x [1024,3072]
    tf32_gemm<<<dim3(3*E_/BN, NROWS/BM), 256, GSMEM>>>(
        h, wqkv, qkv, NROWS, 3*E_, E_, nullptr, nullptr, 0);
    // 3) causal attention
    attn_kernel<<<dim3(T_/64, B_*H_), 64>>>(qkv, attn);
    // 4) x1 = x + attn @ Wp + bp
    tf32_gemm<<<dim3(E_/BN, NROWS/BM), 256, GSMEM>>>(
        attn, Wp, x1, NROWS, E_, E_, bp, x, 0);
    // 5) h2 = LN2(x1)
    ln_kernel<<<NROWS, 256>>>(x1, g2, be2, h2);
    // 6) ff1 = relu(h2 @ W1 + b1)
    tf32_gemm<<<dim3(FF/BN, NROWS/BM), 256, GSMEM>>>(
        h2, W1, ff1, NROWS, FF, E_, b1, nullptr, 1);
    // 7) out = x1 + ff1 @ W2 + b2   (K = 4096)
    tf32_gemm<<<dim3(E_/BN, NROWS/BM), 256, GSMEM>>>(
        ff1, W2, out, NROWS, E_, FF, b2, x1, 0);
}

// round 7
// speedup vs baseline: 1.4879x; 1.0965x over previous
#include <cuda_runtime.h>
#include <math.h>
#include <stdint.h>
#include <mma.h>

using namespace nvcuda;

#define B_  2
#define T_  2048
#define E_  1024
#define H_  16
#define HS_ 64
#define NROWS (B_*T_)   // 4096 rows
#define FF  (4*E_)      // 4096

// ---------------- scratch ----------------------------------------------------
__device__ float g_h   [NROWS * E_];     // LN1 output
__device__ float g_wqkv[E_ * 3 * E_];    // repacked QKV weights [E, 3E]
__device__ float g_qkv [NROWS * 3 * E_]; // Q|K|V per row
__device__ float g_attn[NROWS * E_];     // attention out
__device__ float g_x1  [NROWS * E_];     // residual 1
__device__ float g_h2  [NROWS * E_];     // LN2 output
__device__ float g_ff1 [NROWS * FF];     // FFN hidden

// ---------------- LayerNorm --------------------------------------------------
__global__ __launch_bounds__(256) void ln_kernel(const float* __restrict__ x,
                                                 const float* __restrict__ g,
                                                 const float* __restrict__ b,
                                                 float* __restrict__ out)
{
    int row = blockIdx.x;
    int tid = threadIdx.x;
    const float4* xr = reinterpret_cast<const float4*>(x + (size_t)row * E_);
    float4 v = xr[tid];
    float s  = v.x + v.y + v.z + v.w;
    float sq = v.x*v.x + v.y*v.y + v.z*v.z + v.w*v.w;

    __shared__ float sh[16];
    __shared__ float s_mu, s_rs;
    #pragma unroll
    for (int o = 16; o > 0; o >>= 1) {
        s  += __shfl_down_sync(0xffffffffu, s,  o);
        sq += __shfl_down_sync(0xffffffffu, sq, o);
    }
    int lane = tid & 31, wid = tid >> 5;
    if (lane == 0) { sh[wid] = s; sh[8 + wid] = sq; }
    __syncthreads();
    if (tid == 0) {
        float ts = 0.f, tq = 0.f;
        #pragma unroll
        for (int w = 0; w < 8; w++) { ts += sh[w]; tq += sh[8 + w]; }
        float mu  = ts * (1.0f / E_);
        float var = tq * (1.0f / E_) - mu * mu;
        s_mu = mu;
        s_rs = rsqrtf(var + 1e-5f);
    }
    __syncthreads();
    float mu = s_mu, rs = s_rs;
    float4 gg = reinterpret_cast<const float4*>(g)[tid];
    float4 bb = reinterpret_cast<const float4*>(b)[tid];
    float4 r;
    r.x = (v.x - mu) * rs * gg.x + bb.x;
    r.y = (v.y - mu) * rs * gg.y + bb.y;
    r.z = (v.z - mu) * rs * gg.z + bb.z;
    r.w = (v.w - mu) * rs * gg.w + bb.w;
    reinterpret_cast<float4*>(out + (size_t)row * E_)[tid] = r;
}

// ---------------- Repack Wq/Wk/Wv [H,E,HS] -> [E, 3E] ------------------------
__global__ void repack_kernel(const float* __restrict__ Wq,
                              const float* __restrict__ Wk,
                              const float* __restrict__ Wv,
                              float* __restrict__ Wqkv)
{
    int i = blockIdx.x * blockDim.x + threadIdx.x;   // over H*E*HS = 1M
    if (i >= H_ * E_ * HS_) return;
    int h = i / (E_ * HS_);
    int r = i % (E_ * HS_);
    int e = r / HS_;
    int d = r % HS_;
    int col = h * HS_ + d;
    size_t base = (size_t)e * (3 * E_);
    Wqkv[base + col]           = Wq[i];
    Wqkv[base + E_ + col]      = Wk[i];
    Wqkv[base + 2 * E_ + col]  = Wv[i];
}

// ---------------- WMMA TF32 GEMM --------------------------------------------
// C[M,N] = A[M,K] @ Bm[K,N]   (+bias per col, optional ReLU, optional +res)
// Tile 128x128, BK=32, 128 threads (4 warps, each 64x64), 3-stage cp.async.
#define BM   128
#define BN   128
#define BKC  32
#define AST  36                    // A smem row stride (floats)
#define BST  132                   // B smem row stride (floats)
#define STAGE_F (BM*AST + BKC*BST) // 4608 + 4224 = 8832 floats / stage
#define NSTG 3
#define GSMEM (NSTG * STAGE_F * 4) // 105984 bytes

__device__ __forceinline__ void cp_async16(uint32_t dst, const void* src) {
    asm volatile("cp.async.cg.shared.global [%0], [%1], 16;" :: "r"(dst), "l"(src));
}

__global__ __launch_bounds__(128, 2) void tf32_gemm(
    const float* __restrict__ A, const float* __restrict__ Bm,
    float* __restrict__ C, int M, int N, int K,
    const float* __restrict__ bias, const float* __restrict__ res, int relu)
{
    extern __shared__ float sm[];
    uint32_t sm_u32;
    asm("{ .reg .u64 t; cvta.to.shared.u64 t, %1; cvt.u32.u64 %0, t; }"
        : "=r"(sm_u32) : "l"(sm));

    int tid  = threadIdx.x;
    int wid  = tid >> 5;
    int wm   = wid & 1;        // 0..1  -> 64-row slab
    int wn   = wid >> 1;       // 0..1  -> 64-col slab
    int m0   = blockIdx.y * BM;
    int n0   = blockIdx.x * BN;
    int NC   = K / BKC;

    wmma::fragment<wmma::accumulator, 16, 16, 8, float> acc[4][4];
    #pragma unroll
    for (int i = 0; i < 4; i++)
        #pragma unroll
        for (int j = 0; j < 4; j++)
            wmma::fill_fragment(acc[i][j], 0.0f);

    // ---- async tile loader: A 1024x16B + B 1024x16B, 16 ops/thread ----
    auto issue = [&](int c) {
        int buf = c % NSTG;
        uint32_t stA = sm_u32 + (uint32_t)(buf * STAGE_F) * 4u;
        uint32_t stB = stA + (uint32_t)(BM * AST) * 4u;
        int k0 = c * BKC;
        #pragma unroll
        for (int t = 0; t < 8; t++) {
            int idx = tid + t * 128;
            int r  = idx >> 3;            // 0..127
            int kk = (idx & 7) * 4;       // 0..28
            cp_async16(stA + (uint32_t)(r * AST + kk) * 4u,
                       A + (size_t)(m0 + r) * K + k0 + kk);
        }
        #pragma unroll
        for (int t = 0; t < 8; t++) {
            int idx = tid + t * 128;
            int r  = idx >> 5;            // 0..31
            int nn = (idx & 31) * 4;      // 0..124
            cp_async16(stB + (uint32_t)(r * BST + nn) * 4u,
                       Bm + (size_t)(k0 + r) * N + n0 + nn);
        }
        asm volatile("cp.async.commit_group;" ::: "memory");
    };

    issue(0);
    if (NC > 1) issue(1);

    for (int c = 0; c < NC; c++) {
        if (c + 2 < NC) {
            issue(c + 2);
            asm volatile("cp.async.wait_group 2;" ::: "memory");
        } else if (c + 1 < NC) {
            asm volatile("cp.async.wait_group 1;" ::: "memory");
        } else {
            asm volatile("cp.async.wait_group 0;" ::: "memory");
        }
        __syncthreads();

        const float* sA = sm + (c % NSTG) * STAGE_F;
        const float* sB = sA + BM * AST;

        #pragma unroll
        for (int kk = 0; kk < 4; kk++) {
            wmma::fragment<wmma::matrix_a, 16, 16, 8, wmma::precision::tf32, wmma::row_major> af[4];
            wmma::fragment<wmma::matrix_b, 16, 16, 8, wmma::precision::tf32, wmma::row_major> bf[4];
            #pragma unroll
            for (int i = 0; i < 4; i++) {
                wmma::load_matrix_sync(af[i], sA + (wm * 64 + i * 16) * AST + kk * 8, AST);
                #pragma unroll
                for (int t = 0; t < af[i].num_elements; t++)
                    af[i].x[t] = wmma::__float_to_tf32(af[i].x[t]);
            }
            #pragma unroll
            for (int j = 0; j < 4; j++) {
                wmma::load_matrix_sync(bf[j], sB + (kk * 8) * BST + wn * 64 + j * 16, BST);
                #pragma unroll
                for (int t = 0; t < bf[j].num_elements; t++)
                    bf[j].x[t] = wmma::__float_to_tf32(bf[j].x[t]);
            }
            #pragma unroll
            for (int i = 0; i < 4; i++)
                #pragma unroll
                for (int j = 0; j < 4; j++)
                    wmma::mma_sync(acc[i][j], af[i], bf[j], acc[i][j]);
        }
        __syncthreads();
    }

    // ---- epilogue: fragments -> smem staging -> global with bias/relu/res ----
    float* Cs = sm;   // reuse (128 x BST staging = 67584 B <= GSMEM)
    #pragma unroll
    for (int i = 0; i < 4; i++)
        #pragma unroll
        for (int j = 0; j < 4; j++)
            wmma::store_matrix_sync(Cs + (wm * 64 + i * 16) * BST + wn * 64 + j * 16,
                                    acc[i][j], BST, wmma::mem_row_major);
    __syncthreads();

    for (int idx = tid; idx < BM * BN / 4; idx += 128) {
        int r  = idx >> 5;        // 0..127
        int c4 = idx & 31;        // 0..31  (float4 col)
        float4 v = *reinterpret_cast<const float4*>(Cs + r * BST + c4 * 4);
        int col = n0 + c4 * 4;
        size_t row = (size_t)(m0 + r);
        if (bias) {
            float4 bb = *reinterpret_cast<const float4*>(bias + col);
            v.x += bb.x; v.y += bb.y; v.z += bb.z; v.w += bb.w;
        }
        if (relu) {
            v.x = fmaxf(v.x, 0.f); v.y = fmaxf(v.y, 0.f);
            v.z = fmaxf(v.z, 0.f); v.w = fmaxf(v.w, 0.f);
        }
        if (res) {
            float4 rr = *reinterpret_cast<const float4*>(res + row * N + col);
            v.x += rr.x; v.y += rr.y; v.z += rr.z; v.w += rr.w;
        }
        *reinterpret_cast<float4*>(C + row * N + col) = v;
    }
}

// ---------------- Causal flash attention (unchanged, known-good) -------------
__global__ __launch_bounds__(64) void attn_kernel(const float* __restrict__ qkv,
                                                  float* __restrict__ out)
{
    __shared__ float Ks[64 * 64];
    __shared__ float Vs[64 * 64];
    __shared__ float Ss[64 * 64];

    int tid = threadIdx.x;
    int qt  = blockIdx.x;
    int bh  = blockIdx.y;
    int b = bh >> 4, h = bh & 15;
    int qi = qt * 64 + tid;
    const float scale = 0.125f;

    float q[64], o[64];
    const float* qrow = qkv + (size_t)(b * T_ + qi) * (3 * E_) + h * HS_;
    #pragma unroll
    for (int k = 0; k < 64; k++) q[k] = qrow[k] * scale;
    #pragma unroll
    for (int k = 0; k < 64; k++) o[k] = 0.f;
    float m = -1e30f, l = 0.f;

    int sw = tid & 31;

    for (int kt = 0; kt <= qt; kt++) {
        const float* kbase = qkv + (size_t)(b * T_ + kt * 64) * (3 * E_) + E_ + h * HS_;
        const float* vbase = kbase + E_;
        for (int r = 0; r < 64; r++) {
            Ks[r * 64 + tid] = kbase[(size_t)r * (3 * E_) + tid];
            Vs[r * 64 + tid] = vbase[(size_t)r * (3 * E_) + tid];
        }
        __syncthreads();

        int jmax = (kt == qt) ? (tid + 1) : 64;
        float mt = -1e30f;
        for (int j = 0; j < jmax; j++) {
            float s = 0.f;
            #pragma unroll
            for (int k = 0; k < 64; k++) s += q[k] * Ks[j * 64 + k];
            Ss[tid * 64 + (j ^ sw)] = s;
            mt = fmaxf(mt, s);
        }
        float mn = fmaxf(m, mt);
        float corr = __expf(m - mn);
        #pragma unroll
        for (int k = 0; k < 64; k++) o[k] *= corr;
        l *= corr;
        m = mn;
        for (int j = 0; j < jmax; j++) {
            float p = __expf(Ss[tid * 64 + (j ^ sw)] - m);
            l += p;
            #pragma unroll
            for (int k = 0; k < 64; k++) o[k] += p * Vs[j * 64 + k];
        }
        __syncthreads();
    }

    float inv = 1.f / l;
    float* orow = out + (size_t)(b * T_ + qi) * E_ + h * HS_;
    #pragma unroll
    for (int k = 0; k < 64; k++) orow[k] = o[k] * inv;
}

// ---------------- host -------------------------------------------------------
extern "C" void kernel_launch(void* const* d_in, const int* in_sizes, int n_in,
                              void* d_out, int out_size)
{
    const float* x   = (const float*)d_in[0];
    const float* Wq  = (const float*)d_in[1];
    const float* Wk  = (const float*)d_in[2];
    const float* Wv  = (const float*)d_in[3];
    const float* Wp  = (const float*)d_in[4];
    const float* bp  = (const float*)d_in[5];
    const float* W1  = (const float*)d_in[6];
    const float* b1  = (const float*)d_in[7];
    const float* W2  = (const float*)d_in[8];
    const float* b2  = (const float*)d_in[9];
    const float* g1  = (const float*)d_in[10];
    const float* be1 = (const float*)d_in[11];
    const float* g2  = (const float*)d_in[12];
    const float* be2 = (const float*)d_in[13];
    float* out = (float*)d_out;

    float *h, *wqkv, *qkv, *attn, *x1, *h2, *ff1;
    cudaGetSymbolAddress((void**)&h,    g_h);
    cudaGetSymbolAddress((void**)&wqkv, g_wqkv);
    cudaGetSymbolAddress((void**)&qkv,  g_qkv);
    cudaGetSymbolAddress((void**)&attn, g_attn);
    cudaGetSymbolAddress((void**)&x1,   g_x1);
    cudaGetSymbolAddress((void**)&h2,   g_h2);
    cudaGetSymbolAddress((void**)&ff1,  g_ff1);

    cudaFuncSetAttribute(tf32_gemm, cudaFuncAttributeMaxDynamicSharedMemorySize, GSMEM);

    // 1) h = LN1(x); repack QKV weights
    ln_kernel<<<NROWS, 256>>>(x, g1, be1, h);
    repack_kernel<<<(H_ * E_ * HS_ + 255) / 256, 256>>>(Wq, Wk, Wv, wqkv);
    // 2) QKV = h @ Wqkv        [4096,1024] x [1024,3072]
    tf32_gemm<<<dim3(3*E_/BN, NROWS/BM), 128, GSMEM>>>(
        h, wqkv, qkv, NROWS, 3*E_, E_, nullptr, nullptr, 0);
    // 3) causal attention
    attn_kernel<<<dim3(T_/64, B_*H_), 64>>>(qkv, attn);
    // 4) x1 = x + attn @ Wp + bp
    tf32_gemm<<<dim3(E_/BN, NROWS/BM), 128, GSMEM>>>(
        attn, Wp, x1, NROWS, E_, E_, bp, x, 0);
    // 5) h2 = LN2(x1)
    ln_kernel<<<NROWS, 256>>>(x1, g2, be2, h2);
    // 6) ff1 = relu(h2 @ W1 + b1)
    tf32_gemm<<<dim3(FF/BN, NROWS/BM), 128, GSMEM>>>(
        h2, W1, ff1, NROWS, FF, E_, b1, nullptr, 1);
    // 7) out = x1 + ff1 @ W2 + b2   (K = 4096)
    tf32_gemm<<<dim3(E_/BN, NROWS/BM), 128, GSMEM>>>(
        ff1, W2, out, NROWS, E_, FF, b2, x1, 0);
}

// round 8
// speedup vs baseline: 2.1954x; 1.4755x over previous
#include <cuda_runtime.h>
#include <math.h>
#include <stdint.h>
#include <mma.h>

using namespace nvcuda;

#define B_  2
#define T_  2048
#define E_  1024
#define H_  16
#define HS_ 64
#define NROWS (B_*T_)   // 4096 rows
#define FF  (4*E_)      // 4096

// ---------------- scratch ----------------------------------------------------
__device__ float g_h   [NROWS * E_];     // LN1 output
__device__ float g_wqkv[E_ * 3 * E_];    // repacked QKV weights [E, 3E]
__device__ float g_qkv [NROWS * 3 * E_]; // Q|K|V per row (tf32-rounded)
__device__ float g_attn[NROWS * E_];     // attention out
__device__ float g_x1  [NROWS * E_];     // residual 1
__device__ float g_h2  [NROWS * E_];     // LN2 output
__device__ float g_ff1 [NROWS * FF];     // FFN hidden

__device__ __forceinline__ void cp_async16(uint32_t dst, const void* src) {
    asm volatile("cp.async.cg.shared.global [%0], [%1], 16;" :: "r"(dst), "l"(src));
}
__device__ __forceinline__ uint32_t smem_u32(const void* p) {
    uint32_t a;
    asm("{ .reg .u64 t; cvta.to.shared.u64 t, %1; cvt.u32.u64 %0, t; }" : "=r"(a) : "l"(p));
    return a;
}
__device__ __forceinline__ uint32_t f2tf32(float v) {
    uint32_t u;
    asm("cvt.rna.tf32.f32 %0, %1;" : "=r"(u) : "f"(v));
    return u;
}
// D += A*B, m16n8k8 tf32
__device__ __forceinline__ void mma8(float* c, const uint32_t* a, uint32_t b0, uint32_t b1) {
    asm volatile("mma.sync.aligned.m16n8k8.row.col.f32.tf32.tf32.f32 "
        "{%0,%1,%2,%3}, {%4,%5,%6,%7}, {%8,%9}, {%0,%1,%2,%3};"
        : "+f"(c[0]), "+f"(c[1]), "+f"(c[2]), "+f"(c[3])
        : "r"(a[0]), "r"(a[1]), "r"(a[2]), "r"(a[3]), "r"(b0), "r"(b1));
}

// ---------------- LayerNorm --------------------------------------------------
__global__ __launch_bounds__(256) void ln_kernel(const float* __restrict__ x,
                                                 const float* __restrict__ g,
                                                 const float* __restrict__ b,
                                                 float* __restrict__ out)
{
    int row = blockIdx.x;
    int tid = threadIdx.x;
    const float4* xr = reinterpret_cast<const float4*>(x + (size_t)row * E_);
    float4 v = xr[tid];
    float s  = v.x + v.y + v.z + v.w;
    float sq = v.x*v.x + v.y*v.y + v.z*v.z + v.w*v.w;

    __shared__ float sh[16];
    __shared__ float s_mu, s_rs;
    #pragma unroll
    for (int o = 16; o > 0; o >>= 1) {
        s  += __shfl_down_sync(0xffffffffu, s,  o);
        sq += __shfl_down_sync(0xffffffffu, sq, o);
    }
    int lane = tid & 31, wid = tid >> 5;
    if (lane == 0) { sh[wid] = s; sh[8 + wid] = sq; }
    __syncthreads();
    if (tid == 0) {
        float ts = 0.f, tq = 0.f;
        #pragma unroll
        for (int w = 0; w < 8; w++) { ts += sh[w]; tq += sh[8 + w]; }
        float mu  = ts * (1.0f / E_);
        float var = tq * (1.0f / E_) - mu * mu;
        s_mu = mu;
        s_rs = rsqrtf(var + 1e-5f);
    }
    __syncthreads();
    float mu = s_mu, rs = s_rs;
    float4 gg = reinterpret_cast<const float4*>(g)[tid];
    float4 bb = reinterpret_cast<const float4*>(b)[tid];
    float4 r;
    r.x = (v.x - mu) * rs * gg.x + bb.x;
    r.y = (v.y - mu) * rs * gg.y + bb.y;
    r.z = (v.z - mu) * rs * gg.z + bb.z;
    r.w = (v.w - mu) * rs * gg.w + bb.w;
    reinterpret_cast<float4*>(out + (size_t)row * E_)[tid] = r;
}

// ---------------- Repack Wq/Wk/Wv [H,E,HS] -> [E, 3E] ------------------------
__global__ void repack_kernel(const float* __restrict__ Wq,
                              const float* __restrict__ Wk,
                              const float* __restrict__ Wv,
                              float* __restrict__ Wqkv)
{
    int i = blockIdx.x * blockDim.x + threadIdx.x;
    if (i >= H_ * E_ * HS_) return;
    int h = i / (E_ * HS_);
    int r = i % (E_ * HS_);
    int e = r / HS_;
    int d = r % HS_;
    int col = h * HS_ + d;
    size_t base = (size_t)e * (3 * E_);
    Wqkv[base + col]           = Wq[i];
    Wqkv[base + E_ + col]      = Wk[i];
    Wqkv[base + 2 * E_ + col]  = Wv[i];
}

// ---------------- WMMA TF32 GEMM (unchanged from R6, + optional tf32 round) --
#define BM   128
#define BN   128
#define BKC  32
#define AST  36
#define BST  132
#define STAGE_F (BM*AST + BKC*BST)
#define NSTG 3
#define GSMEM (NSTG * STAGE_F * 4)

__global__ __launch_bounds__(128, 2) void tf32_gemm(
    const float* __restrict__ A, const float* __restrict__ Bm,
    float* __restrict__ C, int M, int N, int K,
    const float* __restrict__ bias, const float* __restrict__ res, int relu,
    int cvt)
{
    extern __shared__ float sm[];
    uint32_t sm_u32a = smem_u32(sm);

    int tid  = threadIdx.x;
    int wid  = tid >> 5;
    int wm   = wid & 1;
    int wn   = wid >> 1;
    int m0   = blockIdx.y * BM;
    int n0   = blockIdx.x * BN;
    int NC   = K / BKC;

    wmma::fragment<wmma::accumulator, 16, 16, 8, float> acc[4][4];
    #pragma unroll
    for (int i = 0; i < 4; i++)
        #pragma unroll
        for (int j = 0; j < 4; j++)
            wmma::fill_fragment(acc[i][j], 0.0f);

    auto issue = [&](int c) {
        int buf = c % NSTG;
        uint32_t stA = sm_u32a + (uint32_t)(buf * STAGE_F) * 4u;
        uint32_t stB = stA + (uint32_t)(BM * AST) * 4u;
        int k0 = c * BKC;
        #pragma unroll
        for (int t = 0; t < 8; t++) {
            int idx = tid + t * 128;
            int r  = idx >> 3;
            int kk = (idx & 7) * 4;
            cp_async16(stA + (uint32_t)(r * AST + kk) * 4u,
                       A + (size_t)(m0 + r) * K + k0 + kk);
        }
        #pragma unroll
        for (int t = 0; t < 8; t++) {
            int idx = tid + t * 128;
            int r  = idx >> 5;
            int nn = (idx & 31) * 4;
            cp_async16(stB + (uint32_t)(r * BST + nn) * 4u,
                       Bm + (size_t)(k0 + r) * N + n0 + nn);
        }
        asm volatile("cp.async.commit_group;" ::: "memory");
    };

    issue(0);
    if (NC > 1) issue(1);

    for (int c = 0; c < NC; c++) {
        if (c + 2 < NC) {
            issue(c + 2);
            asm volatile("cp.async.wait_group 2;" ::: "memory");
        } else if (c + 1 < NC) {
            asm volatile("cp.async.wait_group 1;" ::: "memory");
        } else {
            asm volatile("cp.async.wait_group 0;" ::: "memory");
        }
        __syncthreads();

        const float* sA = sm + (c % NSTG) * STAGE_F;
        const float* sB = sA + BM * AST;

        #pragma unroll
        for (int kk = 0; kk < 4; kk++) {
            wmma::fragment<wmma::matrix_a, 16, 16, 8, wmma::precision::tf32, wmma::row_major> af[4];
            wmma::fragment<wmma::matrix_b, 16, 16, 8, wmma::precision::tf32, wmma::row_major> bf[4];
            #pragma unroll
            for (int i = 0; i < 4; i++) {
                wmma::load_matrix_sync(af[i], sA + (wm * 64 + i * 16) * AST + kk * 8, AST);
                #pragma unroll
                for (int t = 0; t < af[i].num_elements; t++)
                    af[i].x[t] = wmma::__float_to_tf32(af[i].x[t]);
            }
            #pragma unroll
            for (int j = 0; j < 4; j++) {
                wmma::load_matrix_sync(bf[j], sB + (kk * 8) * BST + wn * 64 + j * 16, BST);
                #pragma unroll
                for (int t = 0; t < bf[j].num_elements; t++)
                    bf[j].x[t] = wmma::__float_to_tf32(bf[j].x[t]);
            }
            #pragma unroll
            for (int i = 0; i < 4; i++)
                #pragma unroll
                for (int j = 0; j < 4; j++)
                    wmma::mma_sync(acc[i][j], af[i], bf[j], acc[i][j]);
        }
        __syncthreads();
    }

    float* Cs = sm;
    #pragma unroll
    for (int i = 0; i < 4; i++)
        #pragma unroll
        for (int j = 0; j < 4; j++)
            wmma::store_matrix_sync(Cs + (wm * 64 + i * 16) * BST + wn * 64 + j * 16,
                                    acc[i][j], BST, wmma::mem_row_major);
    __syncthreads();

    for (int idx = tid; idx < BM * BN / 4; idx += 128) {
        int r  = idx >> 5;
        int c4 = idx & 31;
        float4 v = *reinterpret_cast<const float4*>(Cs + r * BST + c4 * 4);
        int col = n0 + c4 * 4;
        size_t row = (size_t)(m0 + r);
        if (bias) {
            float4 bb = *reinterpret_cast<const float4*>(bias + col);
            v.x += bb.x; v.y += bb.y; v.z += bb.z; v.w += bb.w;
        }
        if (relu) {
            v.x = fmaxf(v.x, 0.f); v.y = fmaxf(v.y, 0.f);
            v.z = fmaxf(v.z, 0.f); v.w = fmaxf(v.w, 0.f);
        }
        if (res) {
            float4 rr = *reinterpret_cast<const float4*>(res + row * N + col);
            v.x += rr.x; v.y += rr.y; v.z += rr.z; v.w += rr.w;
        }
        if (cvt) {   // pre-round for tensor-core attention consumers
            v.x = __uint_as_float(f2tf32(v.x));
            v.y = __uint_as_float(f2tf32(v.y));
            v.z = __uint_as_float(f2tf32(v.z));
            v.w = __uint_as_float(f2tf32(v.w));
        }
        *reinterpret_cast<float4*>(C + row * N + col) = v;
    }
}

// ---------------- Tensor-core causal flash attention -------------------------
// 128 threads = 4 warps; warp w owns q rows [16w,16w+16). mma m16n8k8 tf32.
#define AP 76                              // smem row pad (floats)
#define ATT_SMEM (5 * 64 * AP * 4)         // K0,K1,V0,V1,S  = 97280 B

__global__ __launch_bounds__(128) void attn_kernel(const float* __restrict__ qkv,
                                                   float* __restrict__ out)
{
    extern __shared__ float asmem[];
    uint32_t smu = smem_u32(asmem);
    float* Sbuf = asmem + 4 * 64 * AP;

    int tid = threadIdx.x, w = tid >> 5, lane = tid & 31;
    int gid = lane >> 2, tig = lane & 3;
    int qt = (T_ / 64 - 1) - blockIdx.x;     // heavy blocks first
    int bh = blockIdx.y, b = bh >> 4, h = bh & 15;

    const float scale = 0.125f;              // HS^-0.5

    // ---- Q fragments (tf32, scaled), held in registers for all tiles ----
    uint32_t qa[8][4];
    #pragma unroll
    for (int ks = 0; ks < 8; ks++)
        #pragma unroll
        for (int r = 0; r < 4; r++) {
            int row = w * 16 + gid + (r & 1) * 8;
            int col = ks * 8 + tig + (r >> 1) * 4;
            float v = qkv[(size_t)(b * T_ + qt * 64 + row) * (3 * E_) + h * HS_ + col] * scale;
            qa[ks][r] = f2tf32(v);
        }

    float oa[8][4];
    #pragma unroll
    for (int nt = 0; nt < 8; nt++)
        #pragma unroll
        for (int r = 0; r < 4; r++) oa[nt][r] = 0.f;
    float m0 = -1e30f, m1 = -1e30f, l0 = 0.f, l1 = 0.f;

    // ---- K/V tile loader (double buffered, cp.async) ----
    auto loadKV = [&](int kt, int bu) {
        const float* kb = qkv + (size_t)(b * T_ + kt * 64) * (3 * E_) + E_ + h * HS_;
        const float* vb = kb + E_;
        uint32_t kbase = smu + (uint32_t)(bu * 64 * AP) * 4u;
        uint32_t vbase = smu + (uint32_t)((2 + bu) * 64 * AP) * 4u;
        #pragma unroll
        for (int t = 0; t < 8; t++) {
            int i = tid + t * 128;
            int r = i >> 4, c = (i & 15) * 4;
            cp_async16(kbase + (uint32_t)(r * AP + c) * 4u, kb + (size_t)r * (3 * E_) + c);
            cp_async16(vbase + (uint32_t)(r * AP + c) * 4u, vb + (size_t)r * (3 * E_) + c);
        }
        asm volatile("cp.async.commit_group;" ::: "memory");
    };

    loadKV(0, 0);

    for (int kt = 0; kt <= qt; kt++) {
        int bu = kt & 1;
        if (kt < qt) {
            loadKV(kt + 1, bu ^ 1);
            asm volatile("cp.async.wait_group 1;" ::: "memory");
        } else {
            asm volatile("cp.async.wait_group 0;" ::: "memory");
        }
        __syncthreads();

        const float* Ks = asmem + bu * 64 * AP;
        const float* Vs = asmem + (2 + bu) * 64 * AP;

        // ---- S = Q @ K^T ----
        float sa[8][4];
        #pragma unroll
        for (int nt = 0; nt < 8; nt++)
            #pragma unroll
            for (int r = 0; r < 4; r++) sa[nt][r] = 0.f;

        #pragma unroll
        for (int ks = 0; ks < 8; ks++) {
            #pragma unroll
            for (int nt = 0; nt < 8; nt++) {
                uint32_t b0 = __float_as_uint(Ks[(nt * 8 + gid) * AP + ks * 8 + tig]);
                uint32_t b1 = __float_as_uint(Ks[(nt * 8 + gid) * AP + ks * 8 + tig + 4]);
                mma8(sa[nt], qa[ks], b0, b1);
            }
        }

        // ---- causal mask (diagonal tile only) ----
        if (kt == qt) {
            int r0 = w * 16 + gid, r1 = r0 + 8;
            #pragma unroll
            for (int nt = 0; nt < 8; nt++) {
                int c0 = nt * 8 + 2 * tig, c1 = c0 + 1;
                if (c0 > r0) sa[nt][0] = -1e30f;
                if (c1 > r0) sa[nt][1] = -1e30f;
                if (c0 > r1) sa[nt][2] = -1e30f;
                if (c1 > r1) sa[nt][3] = -1e30f;
            }
        }

        // ---- online softmax (registers + quad shuffles) ----
        float mt0 = -1e30f, mt1 = -1e30f;
        #pragma unroll
        for (int nt = 0; nt < 8; nt++) {
            mt0 = fmaxf(mt0, fmaxf(sa[nt][0], sa[nt][1]));
            mt1 = fmaxf(mt1, fmaxf(sa[nt][2], sa[nt][3]));
        }
        mt0 = fmaxf(mt0, __shfl_xor_sync(0xffffffffu, mt0, 1));
        mt0 = fmaxf(mt0, __shfl_xor_sync(0xffffffffu, mt0, 2));
        mt1 = fmaxf(mt1, __shfl_xor_sync(0xffffffffu, mt1, 1));
        mt1 = fmaxf(mt1, __shfl_xor_sync(0xffffffffu, mt1, 2));

        float mn0 = fmaxf(m0, mt0), mn1 = fmaxf(m1, mt1);
        float cr0 = __expf(m0 - mn0), cr1 = __expf(m1 - mn1);
        m0 = mn0; m1 = mn1;

        float s0 = 0.f, s1 = 0.f;
        float* Pr0 = Sbuf + (w * 16 + gid) * AP;
        float* Pr1 = Pr0 + 8 * AP;
        #pragma unroll
        for (int nt = 0; nt < 8; nt++) {
            float p0 = __uint_as_float(f2tf32(__expf(sa[nt][0] - mn0)));
            float p1 = __uint_as_float(f2tf32(__expf(sa[nt][1] - mn0)));
            float p2 = __uint_as_float(f2tf32(__expf(sa[nt][2] - mn1)));
            float p3 = __uint_as_float(f2tf32(__expf(sa[nt][3] - mn1)));
            s0 += p0 + p1;  s1 += p2 + p3;
            *reinterpret_cast<float2*>(Pr0 + nt * 8 + 2 * tig) = make_float2(p0, p1);
            *reinterpret_cast<float2*>(Pr1 + nt * 8 + 2 * tig) = make_float2(p2, p3);
        }
        s0 += __shfl_xor_sync(0xffffffffu, s0, 1);
        s0 += __shfl_xor_sync(0xffffffffu, s0, 2);
        s1 += __shfl_xor_sync(0xffffffffu, s1, 1);
        s1 += __shfl_xor_sync(0xffffffffu, s1, 2);
        l0 = l0 * cr0 + s0;
        l1 = l1 * cr1 + s1;

        #pragma unroll
        for (int nt = 0; nt < 8; nt++) {
            oa[nt][0] *= cr0; oa[nt][1] *= cr0;
            oa[nt][2] *= cr1; oa[nt][3] *= cr1;
        }
        __syncwarp();

        // ---- O += P @ V ----
        #pragma unroll
        for (int ks = 0; ks < 8; ks++) {
            uint32_t pa[4];
            pa[0] = __float_as_uint(Sbuf[(w * 16 + gid) * AP + ks * 8 + tig]);
            pa[1] = __float_as_uint(Sbuf[(w * 16 + gid + 8) * AP + ks * 8 + tig]);
            pa[2] = __float_as_uint(Sbuf[(w * 16 + gid) * AP + ks * 8 + tig + 4]);
            pa[3] = __float_as_uint(Sbuf[(w * 16 + gid + 8) * AP + ks * 8 + tig + 4]);
            #pragma unroll
            for (int nt = 0; nt < 8; nt++) {
                uint32_t b0 = __float_as_uint(Vs[(ks * 8 + tig) * AP + nt * 8 + gid]);
                uint32_t b1 = __float_as_uint(Vs[(ks * 8 + tig + 4) * AP + nt * 8 + gid]);
                mma8(oa[nt], pa, b0, b1);
            }
        }
        __syncthreads();
    }

    // ---- finalize: O /= l, write out ----
    float i0 = 1.f / l0, i1 = 1.f / l1;
    int r0 = qt * 64 + w * 16 + gid;
    #pragma unroll
    for (int nt = 0; nt < 8; nt++) {
        int col = h * HS_ + nt * 8 + 2 * tig;
        float* p0 = out + (size_t)(b * T_ + r0) * E_ + col;
        float* p1 = out + (size_t)(b * T_ + r0 + 8) * E_ + col;
        *reinterpret_cast<float2*>(p0) = make_float2(oa[nt][0] * i0, oa[nt][1] * i0);
        *reinterpret_cast<float2*>(p1) = make_float2(oa[nt][2] * i1, oa[nt][3] * i1);
    }
}

// ---------------- host -------------------------------------------------------
extern "C" void kernel_launch(void* const* d_in, const int* in_sizes, int n_in,
                              void* d_out, int out_size)
{
    const float* x   = (const float*)d_in[0];
    const float* Wq  = (const float*)d_in[1];
    const float* Wk  = (const float*)d_in[2];
    const float* Wv  = (const float*)d_in[3];
    const float* Wp  = (const float*)d_in[4];
    const float* bp  = (const float*)d_in[5];
    const float* W1  = (const float*)d_in[6];
    const float* b1  = (const float*)d_in[7];
    const float* W2  = (const float*)d_in[8];
    const float* b2  = (const float*)d_in[9];
    const float* g1  = (const float*)d_in[10];
    const float* be1 = (const float*)d_in[11];
    const float* g2  = (const float*)d_in[12];
    const float* be2 = (const float*)d_in[13];
    float* out = (float*)d_out;

    float *h, *wqkv, *qkv, *attn, *x1, *h2, *ff1;
    cudaGetSymbolAddress((void**)&h,    g_h);
    cudaGetSymbolAddress((void**)&wqkv, g_wqkv);
    cudaGetSymbolAddress((void**)&qkv,  g_qkv);
    cudaGetSymbolAddress((void**)&attn, g_attn);
    cudaGetSymbolAddress((void**)&x1,   g_x1);
    cudaGetSymbolAddress((void**)&h2,   g_h2);
    cudaGetSymbolAddress((void**)&ff1,  g_ff1);

    cudaFuncSetAttribute(tf32_gemm, cudaFuncAttributeMaxDynamicSharedMemorySize, GSMEM);
    cudaFuncSetAttribute(attn_kernel, cudaFuncAttributeMaxDynamicSharedMemorySize, ATT_SMEM);

    // 1) h = LN1(x); repack QKV weights
    ln_kernel<<<NROWS, 256>>>(x, g1, be1, h);
    repack_kernel<<<(H_ * E_ * HS_ + 255) / 256, 256>>>(Wq, Wk, Wv, wqkv);
    // 2) QKV = h @ Wqkv (tf32-rounded output for attention)
    tf32_gemm<<<dim3(3*E_/BN, NROWS/BM), 128, GSMEM>>>(
        h, wqkv, qkv, NROWS, 3*E_, E_, nullptr, nullptr, 0, 1);
    // 3) causal attention (tensor cores)
    attn_kernel<<<dim3(T_/64, B_*H_), 128, ATT_SMEM>>>(qkv, attn);
    // 4) x1 = x + attn @ Wp + bp
    tf32_gemm<<<dim3(E_/BN, NROWS/BM), 128, GSMEM>>>(
        attn, Wp, x1, NROWS, E_, E_, bp, x, 0, 0);
    // 5) h2 = LN2(x1)
    ln_kernel<<<NROWS, 256>>>(x1, g2, be2, h2);
    // 6) ff1 = relu(h2 @ W1 + b1)
    tf32_gemm<<<dim3(FF/BN, NROWS/BM), 128, GSMEM>>>(
        h2, W1, ff1, NROWS, FF, E_, b1, nullptr, 1, 0);
    // 7) out = x1 + ff1 @ W2 + b2
    tf32_gemm<<<dim3(E_/BN, NROWS/BM), 128, GSMEM>>>(
        ff1, W2, out, NROWS, E_, FF, b2, x1, 0, 0);
}

// round 9
// speedup vs baseline: 5.8671x; 2.6725x over previous
#include <cuda_runtime.h>
#include <cuda_fp16.h>
#include <math.h>
#include <stdint.h>
#include <mma.h>

using namespace nvcuda;

#define B_  2
#define T_  2048
#define E_  1024
#define H_  16
#define HS_ 64
#define NROWS (B_*T_)   // 4096 rows
#define FF  (4*E_)      // 4096

// ---------------- scratch ----------------------------------------------------
__device__ __half g_h16  [NROWS * E_];      // LN1 output (fp16)
__device__ __half g_wqkv16[E_ * 3 * E_];    // repacked QKV weights [E,3E] fp16
__device__ __half g_wp16 [E_ * E_];
__device__ __half g_w116 [E_ * FF];
__device__ __half g_w216 [FF * E_];
__device__ float  g_qkv  [NROWS * 3 * E_];  // Q|K|V fp32 (tf32-rounded)
__device__ __half g_attn16[NROWS * E_];     // attention out fp16
__device__ float  g_x1   [NROWS * E_];      // residual 1 (fp32)
__device__ __half g_h2_16[NROWS * E_];      // LN2 output fp16
__device__ __half g_ff116[NROWS * FF];      // FFN hidden fp16

__device__ __forceinline__ void cp_async16(uint32_t dst, const void* src) {
    asm volatile("cp.async.cg.shared.global [%0], [%1], 16;" :: "r"(dst), "l"(src));
}
__device__ __forceinline__ uint32_t smem_u32(const void* p) {
    uint32_t a;
    asm("{ .reg .u64 t; cvta.to.shared.u64 t, %1; cvt.u32.u64 %0, t; }" : "=r"(a) : "l"(p));
    return a;
}
__device__ __forceinline__ uint32_t f2tf32(float v) {
    uint32_t u;
    asm("cvt.rna.tf32.f32 %0, %1;" : "=r"(u) : "f"(v));
    return u;
}
__device__ __forceinline__ void mma8(float* c, const uint32_t* a, uint32_t b0, uint32_t b1) {
    asm volatile("mma.sync.aligned.m16n8k8.row.col.f32.tf32.tf32.f32 "
        "{%0,%1,%2,%3}, {%4,%5,%6,%7}, {%8,%9}, {%0,%1,%2,%3};"
        : "+f"(c[0]), "+f"(c[1]), "+f"(c[2]), "+f"(c[3])
        : "r"(a[0]), "r"(a[1]), "r"(a[2]), "r"(a[3]), "r"(b0), "r"(b1));
}

// ---------------- LayerNorm (fp32 in -> fp16 out) ----------------------------
__global__ __launch_bounds__(256) void ln_kernel(const float* __restrict__ x,
                                                 const float* __restrict__ g,
                                                 const float* __restrict__ b,
                                                 __half* __restrict__ out)
{
    int row = blockIdx.x;
    int tid = threadIdx.x;
    const float4* xr = reinterpret_cast<const float4*>(x + (size_t)row * E_);
    float4 v = xr[tid];
    float s  = v.x + v.y + v.z + v.w;
    float sq = v.x*v.x + v.y*v.y + v.z*v.z + v.w*v.w;

    __shared__ float sh[16];
    __shared__ float s_mu, s_rs;
    #pragma unroll
    for (int o = 16; o > 0; o >>= 1) {
        s  += __shfl_down_sync(0xffffffffu, s,  o);
        sq += __shfl_down_sync(0xffffffffu, sq, o);
    }
    int lane = tid & 31, wid = tid >> 5;
    if (lane == 0) { sh[wid] = s; sh[8 + wid] = sq; }
    __syncthreads();
    if (tid == 0) {
        float ts = 0.f, tq = 0.f;
        #pragma unroll
        for (int w = 0; w < 8; w++) { ts += sh[w]; tq += sh[8 + w]; }
        float mu  = ts * (1.0f / E_);
        float var = tq * (1.0f / E_) - mu * mu;
        s_mu = mu;
        s_rs = rsqrtf(var + 1e-5f);
    }
    __syncthreads();
    float mu = s_mu, rs = s_rs;
    float4 gg = reinterpret_cast<const float4*>(g)[tid];
    float4 bb = reinterpret_cast<const float4*>(b)[tid];
    __half2 h0 = __floats2half2_rn((v.x - mu) * rs * gg.x + bb.x,
                                   (v.y - mu) * rs * gg.y + bb.y);
    __half2 h1 = __floats2half2_rn((v.z - mu) * rs * gg.z + bb.z,
                                   (v.w - mu) * rs * gg.w + bb.w);
    __half2* op = reinterpret_cast<__half2*>(out + (size_t)row * E_ + tid * 4);
    op[0] = h0; op[1] = h1;
}

// ---------------- fp32 -> fp16 convert ---------------------------------------
__global__ void f2h_kernel(const float* __restrict__ in, __half* __restrict__ out, int n)
{
    int i = blockIdx.x * blockDim.x + threadIdx.x;
    if (i < n) out[i] = __float2half(in[i]);
}

// ---------------- Repack Wq/Wk/Wv [H,E,HS] -> [E, 3E] fp16 -------------------
__global__ void repack_kernel(const float* __restrict__ Wq,
                              const float* __restrict__ Wk,
                              const float* __restrict__ Wv,
                              __half* __restrict__ Wqkv)
{
    int i = blockIdx.x * blockDim.x + threadIdx.x;
    if (i >= H_ * E_ * HS_) return;
    int h = i / (E_ * HS_);
    int r = i % (E_ * HS_);
    int e = r / HS_;
    int d = r % HS_;
    int col = h * HS_ + d;
    size_t base = (size_t)e * (3 * E_);
    Wqkv[base + col]           = __float2half(Wq[i]);
    Wqkv[base + E_ + col]      = __float2half(Wk[i]);
    Wqkv[base + 2 * E_ + col]  = __float2half(Wv[i]);
}

// ---------------- fp16 WMMA GEMM (m16n16k16, fp32 accum) ---------------------
// C[M,N] = A[M,K] @ Bm[K,N]  A,B fp16.  +bias / ReLU / +res; out fp32 C or fp16 Ch.
#define BM   128
#define BN   128
#define BKC  32
#define ASTH 40                      // A smem row stride (halves)
#define BSTH 136                     // B smem row stride (halves)
#define STAGE_H (BM*ASTH + BKC*BSTH) // 5120 + 4352 = 9472 halves / stage
#define NSTG 3
#define CST  132                     // epilogue staging stride (floats)
#define GSMEM (BM * CST * 4)         // 67584 B  (> 3*STAGE_H*2 = 56832)

__global__ __launch_bounds__(128, 2) void h16_gemm(
    const __half* __restrict__ A, const __half* __restrict__ Bm,
    float* __restrict__ C, __half* __restrict__ Ch, int M, int N, int K,
    const float* __restrict__ bias, const float* __restrict__ res, int relu,
    int cvt)
{
    extern __shared__ float sm[];
    __half* smh = reinterpret_cast<__half*>(sm);
    uint32_t smb = smem_u32(sm);

    int tid  = threadIdx.x;
    int wid  = tid >> 5;
    int wm   = wid & 1;
    int wn   = wid >> 1;
    int m0   = blockIdx.y * BM;
    int n0   = blockIdx.x * BN;
    int NC   = K / BKC;

    wmma::fragment<wmma::accumulator, 16, 16, 16, float> acc[4][4];
    #pragma unroll
    for (int i = 0; i < 4; i++)
        #pragma unroll
        for (int j = 0; j < 4; j++)
            wmma::fill_fragment(acc[i][j], 0.0f);

    // per stage: A 8192B + B 8192B = 1024 x 16B ops; 8 per thread
    auto issue = [&](int c) {
        int buf = c % NSTG;
        uint32_t stA = smb + (uint32_t)(buf * STAGE_H) * 2u;
        uint32_t stB = stA + (uint32_t)(BM * ASTH) * 2u;
        int k0 = c * BKC;
        #pragma unroll
        for (int t = 0; t < 4; t++) {
            int idx = tid + t * 128;
            int r  = idx >> 2;            // 0..127
            int kk = (idx & 3) * 8;       // halves, 0..24
            cp_async16(stA + (uint32_t)(r * ASTH + kk) * 2u,
                       A + (size_t)(m0 + r) * K + k0 + kk);
        }
        #pragma unroll
        for (int t = 0; t < 4; t++) {
            int idx = tid + t * 128;
            int r  = idx >> 4;            // 0..31
            int nn = (idx & 15) * 8;      // halves, 0..120
            cp_async16(stB + (uint32_t)(r * BSTH + nn) * 2u,
                       Bm + (size_t)(k0 + r) * N + n0 + nn);
        }
        asm volatile("cp.async.commit_group;" ::: "memory");
    };

    issue(0);
    if (NC > 1) issue(1);

    for (int c = 0; c < NC; c++) {
        if (c + 2 < NC) {
            issue(c + 2);
            asm volatile("cp.async.wait_group 2;" ::: "memory");
        } else if (c + 1 < NC) {
            asm volatile("cp.async.wait_group 1;" ::: "memory");
        } else {
            asm volatile("cp.async.wait_group 0;" ::: "memory");
        }
        __syncthreads();

        const __half* sA = smh + (c % NSTG) * STAGE_H;
        const __half* sB = sA + BM * ASTH;

        #pragma unroll
        for (int kk = 0; kk < 2; kk++) {            // two k16 chunks
            wmma::fragment<wmma::matrix_a, 16, 16, 16, __half, wmma::row_major> af[4];
            wmma::fragment<wmma::matrix_b, 16, 16, 16, __half, wmma::row_major> bf[4];
            #pragma unroll
            for (int i = 0; i < 4; i++)
                wmma::load_matrix_sync(af[i], sA + (wm * 64 + i * 16) * ASTH + kk * 16, ASTH);
            #pragma unroll
            for (int j = 0; j < 4; j++)
                wmma::load_matrix_sync(bf[j], sB + (kk * 16) * BSTH + wn * 64 + j * 16, BSTH);
            #pragma unroll
            for (int i = 0; i < 4; i++)
                #pragma unroll
                for (int j = 0; j < 4; j++)
                    wmma::mma_sync(acc[i][j], af[i], bf[j], acc[i][j]);
        }
        __syncthreads();
    }

    // ---- epilogue ----
    float* Cs = sm;
    #pragma unroll
    for (int i = 0; i < 4; i++)
        #pragma unroll
        for (int j = 0; j < 4; j++)
            wmma::store_matrix_sync(Cs + (wm * 64 + i * 16) * CST + wn * 64 + j * 16,
                                    acc[i][j], CST, wmma::mem_row_major);
    __syncthreads();

    for (int idx = tid; idx < BM * BN / 4; idx += 128) {
        int r  = idx >> 5;
        int c4 = idx & 31;
        float4 v = *reinterpret_cast<const float4*>(Cs + r * CST + c4 * 4);
        int col = n0 + c4 * 4;
        size_t row = (size_t)(m0 + r);
        if (bias) {
            float4 bb = *reinterpret_cast<const float4*>(bias + col);
            v.x += bb.x; v.y += bb.y; v.z += bb.z; v.w += bb.w;
        }
        if (relu) {
            v.x = fmaxf(v.x, 0.f); v.y = fmaxf(v.y, 0.f);
            v.z = fmaxf(v.z, 0.f); v.w = fmaxf(v.w, 0.f);
        }
        if (res) {
            float4 rr = *reinterpret_cast<const float4*>(res + row * N + col);
            v.x += rr.x; v.y += rr.y; v.z += rr.z; v.w += rr.w;
        }
        if (Ch) {
            __half2* hp = reinterpret_cast<__half2*>(Ch + row * N + col);
            hp[0] = __floats2half2_rn(v.x, v.y);
            hp[1] = __floats2half2_rn(v.z, v.w);
        } else {
            if (cvt) {
                v.x = __uint_as_float(f2tf32(v.x));
                v.y = __uint_as_float(f2tf32(v.y));
                v.z = __uint_as_float(f2tf32(v.z));
                v.w = __uint_as_float(f2tf32(v.w));
            }
            *reinterpret_cast<float4*>(C + row * N + col) = v;
        }
    }
}

// ---------------- Tensor-core causal flash attention (tf32) ------------------
#define AP 76
#define ATT_SMEM (5 * 64 * AP * 4)

__global__ __launch_bounds__(128) void attn_kernel(const float* __restrict__ qkv,
                                                   __half* __restrict__ out)
{
    extern __shared__ float asmem[];
    uint32_t smu = smem_u32(asmem);
    float* Sbuf = asmem + 4 * 64 * AP;

    int tid = threadIdx.x, w = tid >> 5, lane = tid & 31;
    int gid = lane >> 2, tig = lane & 3;
    int qt = (T_ / 64 - 1) - blockIdx.x;
    int bh = blockIdx.y, b = bh >> 4, h = bh & 15;

    const float scale = 0.125f;

    uint32_t qa[8][4];
    #pragma unroll
    for (int ks = 0; ks < 8; ks++)
        #pragma unroll
        for (int r = 0; r < 4; r++) {
            int row = w * 16 + gid + (r & 1) * 8;
            int col = ks * 8 + tig + (r >> 1) * 4;
            float v = qkv[(size_t)(b * T_ + qt * 64 + row) * (3 * E_) + h * HS_ + col] * scale;
            qa[ks][r] = f2tf32(v);
        }

    float oa[8][4];
    #pragma unroll
    for (int nt = 0; nt < 8; nt++)
        #pragma unroll
        for (int r = 0; r < 4; r++) oa[nt][r] = 0.f;
    float m0 = -1e30f, m1 = -1e30f, l0 = 0.f, l1 = 0.f;

    auto loadKV = [&](int kt, int bu) {
        const float* kb = qkv + (size_t)(b * T_ + kt * 64) * (3 * E_) + E_ + h * HS_;
        const float* vb = kb + E_;
        uint32_t kbase = smu + (uint32_t)(bu * 64 * AP) * 4u;
        uint32_t vbase = smu + (uint32_t)((2 + bu) * 64 * AP) * 4u;
        #pragma unroll
        for (int t = 0; t < 8; t++) {
            int i = tid + t * 128;
            int r = i >> 4, c = (i & 15) * 4;
            cp_async16(kbase + (uint32_t)(r * AP + c) * 4u, kb + (size_t)r * (3 * E_) + c);
            cp_async16(vbase + (uint32_t)(r * AP + c) * 4u, vb + (size_t)r * (3 * E_) + c);
        }
        asm volatile("cp.async.commit_group;" ::: "memory");
    };

    loadKV(0, 0);

    for (int kt = 0; kt <= qt; kt++) {
        int bu = kt & 1;
        if (kt < qt) {
            loadKV(kt + 1, bu ^ 1);
            asm volatile("cp.async.wait_group 1;" ::: "memory");
        } else {
            asm volatile("cp.async.wait_group 0;" ::: "memory");
        }
        __syncthreads();

        const float* Ks = asmem + bu * 64 * AP;
        const float* Vs = asmem + (2 + bu) * 64 * AP;

        float sa[8][4];
        #pragma unroll
        for (int nt = 0; nt < 8; nt++)
            #pragma unroll
            for (int r = 0; r < 4; r++) sa[nt][r] = 0.f;

        #pragma unroll
        for (int ks = 0; ks < 8; ks++) {
            #pragma unroll
            for (int nt = 0; nt < 8; nt++) {
                uint32_t b0 = __float_as_uint(Ks[(nt * 8 + gid) * AP + ks * 8 + tig]);
                uint32_t b1 = __float_as_uint(Ks[(nt * 8 + gid) * AP + ks * 8 + tig + 4]);
                mma8(sa[nt], qa[ks], b0, b1);
            }
        }

        if (kt == qt) {
            int r0 = w * 16 + gid, r1 = r0 + 8;
            #pragma unroll
            for (int nt = 0; nt < 8; nt++) {
                int c0 = nt * 8 + 2 * tig, c1 = c0 + 1;
                if (c0 > r0) sa[nt][0] = -1e30f;
                if (c1 > r0) sa[nt][1] = -1e30f;
                if (c0 > r1) sa[nt][2] = -1e30f;
                if (c1 > r1) sa[nt][3] = -1e30f;
            }
        }

        float mt0 = -1e30f, mt1 = -1e30f;
        #pragma unroll
        for (int nt = 0; nt < 8; nt++) {
            mt0 = fmaxf(mt0, fmaxf(sa[nt][0], sa[nt][1]));
            mt1 = fmaxf(mt1, fmaxf(sa[nt][2], sa[nt][3]));
        }
        mt0 = fmaxf(mt0, __shfl_xor_sync(0xffffffffu, mt0, 1));
        mt0 = fmaxf(mt0, __shfl_xor_sync(0xffffffffu, mt0, 2));
        mt1 = fmaxf(mt1, __shfl_xor_sync(0xffffffffu, mt1, 1));
        mt1 = fmaxf(mt1, __shfl_xor_sync(0xffffffffu, mt1, 2));

        float mn0 = fmaxf(m0, mt0), mn1 = fmaxf(m1, mt1);
        float cr0 = __expf(m0 - mn0), cr1 = __expf(m1 - mn1);
        m0 = mn0; m1 = mn1;

        float s0 = 0.f, s1 = 0.f;
        float* Pr0 = Sbuf + (w * 16 + gid) * AP;
        float* Pr1 = Pr0 + 8 * AP;
        #pragma unroll
        for (int nt = 0; nt < 8; nt++) {
            float p0 = __uint_as_float(f2tf32(__expf(sa[nt][0] - mn0)));
            float p1 = __uint_as_float(f2tf32(__expf(sa[nt][1] - mn0)));
            float p2 = __uint_as_float(f2tf32(__expf(sa[nt][2] - mn1)));
            float p3 = __uint_as_float(f2tf32(__expf(sa[nt][3] - mn1)));
            s0 += p0 + p1;  s1 += p2 + p3;
            *reinterpret_cast<float2*>(Pr0 + nt * 8 + 2 * tig) = make_float2(p0, p1);
            *reinterpret_cast<float2*>(Pr1 + nt * 8 + 2 * tig) = make_float2(p2, p3);
        }
        s0 += __shfl_xor_sync(0xffffffffu, s0, 1);
        s0 += __shfl_xor_sync(0xffffffffu, s0, 2);
        s1 += __shfl_xor_sync(0xffffffffu, s1, 1);
        s1 += __shfl_xor_sync(0xffffffffu, s1, 2);
        l0 = l0 * cr0 + s0;
        l1 = l1 * cr1 + s1;

        #pragma unroll
        for (int nt = 0; nt < 8; nt++) {
            oa[nt][0] *= cr0; oa[nt][1] *= cr0;
            oa[nt][2] *= cr1; oa[nt][3] *= cr1;
        }
        __syncwarp();

        #pragma unroll
        for (int ks = 0; ks < 8; ks++) {
            uint32_t pa[4];
            pa[0] = __float_as_uint(Sbuf[(w * 16 + gid) * AP + ks * 8 + tig]);
            pa[1] = __float_as_uint(Sbuf[(w * 16 + gid + 8) * AP + ks * 8 + tig]);
            pa[2] = __float_as_uint(Sbuf[(w * 16 + gid) * AP + ks * 8 + tig + 4]);
            pa[3] = __float_as_uint(Sbuf[(w * 16 + gid + 8) * AP + ks * 8 + tig + 4]);
            #pragma unroll
            for (int nt = 0; nt < 8; nt++) {
                uint32_t b0 = __float_as_uint(Vs[(ks * 8 + tig) * AP + nt * 8 + gid]);
                uint32_t b1 = __float_as_uint(Vs[(ks * 8 + tig + 4) * AP + nt * 8 + gid]);
                mma8(oa[nt], pa, b0, b1);
            }
        }
        __syncthreads();
    }

    float i0 = 1.f / l0, i1 = 1.f / l1;
    int r0 = qt * 64 + w * 16 + gid;
    #pragma unroll
    for (int nt = 0; nt < 8; nt++) {
        int col = h * HS_ + nt * 8 + 2 * tig;
        __half2* p0 = reinterpret_cast<__half2*>(out + (size_t)(b * T_ + r0) * E_ + col);
        __half2* p1 = reinterpret_cast<__half2*>(out + (size_t)(b * T_ + r0 + 8) * E_ + col);
        *p0 = __floats2half2_rn(oa[nt][0] * i0, oa[nt][1] * i0);
        *p1 = __floats2half2_rn(oa[nt][2] * i1, oa[nt][3] * i1);
    }
}

// ---------------- host -------------------------------------------------------
extern "C" void kernel_launch(void* const* d_in, const int* in_sizes, int n_in,
                              void* d_out, int out_size)
{
    const float* x   = (const float*)d_in[0];
    const float* Wq  = (const float*)d_in[1];
    const float* Wk  = (const float*)d_in[2];
    const float* Wv  = (const float*)d_in[3];
    const float* Wp  = (const float*)d_in[4];
    const float* bp  = (const float*)d_in[5];
    const float* W1  = (const float*)d_in[6];
    const float* b1  = (const float*)d_in[7];
    const float* W2  = (const float*)d_in[8];
    const float* b2  = (const float*)d_in[9];
    const float* g1  = (const float*)d_in[10];
    const float* be1 = (const float*)d_in[11];
    const float* g2  = (const float*)d_in[12];
    const float* be2 = (const float*)d_in[13];
    float* out = (float*)d_out;

    __half *h16, *wqkv16, *wp16, *w116, *w216, *attn16, *h2_16, *ff116;
    float *qkv, *x1;
    cudaGetSymbolAddress((void**)&h16,    g_h16);
    cudaGetSymbolAddress((void**)&wqkv16, g_wqkv16);
    cudaGetSymbolAddress((void**)&wp16,   g_wp16);
    cudaGetSymbolAddress((void**)&w116,   g_w116);
    cudaGetSymbolAddress((void**)&w216,   g_w216);
    cudaGetSymbolAddress((void**)&qkv,    g_qkv);
    cudaGetSymbolAddress((void**)&attn16, g_attn16);
    cudaGetSymbolAddress((void**)&x1,     g_x1);
    cudaGetSymbolAddress((void**)&h2_16,  g_h2_16);
    cudaGetSymbolAddress((void**)&ff116,  g_ff116);

    cudaFuncSetAttribute(h16_gemm, cudaFuncAttributeMaxDynamicSharedMemorySize, GSMEM);
    cudaFuncSetAttribute(attn_kernel, cudaFuncAttributeMaxDynamicSharedMemorySize, ATT_SMEM);

    // prep: LN1, weight converts
    ln_kernel<<<NROWS, 256>>>(x, g1, be1, h16);
    repack_kernel<<<(H_ * E_ * HS_ + 255) / 256, 256>>>(Wq, Wk, Wv, wqkv16);
    f2h_kernel<<<(E_ * E_ + 255) / 256, 256>>>(Wp, wp16, E_ * E_);
    f2h_kernel<<<(E_ * FF + 255) / 256, 256>>>(W1, w116, E_ * FF);
    f2h_kernel<<<(FF * E_ + 255) / 256, 256>>>(W2, w216, FF * E_);

    // QKV = h @ Wqkv (fp32 out, tf32-rounded for attention)
    h16_gemm<<<dim3(3*E_/BN, NROWS/BM), 128, GSMEM>>>(
        h16, wqkv16, qkv, nullptr, NROWS, 3*E_, E_, nullptr, nullptr, 0, 1);
    // attention (tf32 tensor cores) -> fp16
    attn_kernel<<<dim3(T_/64, B_*H_), 128, ATT_SMEM>>>(qkv, attn16);
    // x1 = x + attn @ Wp + bp  (fp32 out)
    h16_gemm<<<dim3(E_/BN, NROWS/BM), 128, GSMEM>>>(
        attn16, wp16, x1, nullptr, NROWS, E_, E_, bp, x, 0, 0);
    // h2 = LN2(x1) -> fp16
    ln_kernel<<<NROWS, 256>>>(x1, g2, be2, h2_16);
    // ff1 = relu(h2 @ W1 + b1) -> fp16
    h16_gemm<<<dim3(FF/BN, NROWS/BM), 128, GSMEM>>>(
        h2_16, w116, nullptr, ff116, NROWS, FF, E_, b1, nullptr, 1, 0);
    // out = x1 + ff1 @ W2 + b2  (fp32 out, K = 4096)
    h16_gemm<<<dim3(E_/BN, NROWS/BM), 128, GSMEM>>>(
        ff116, w216, out, nullptr, NROWS, E_, FF, b2, x1, 0, 0);
}

// round 10
// speedup vs baseline: 7.8629x; 1.3402x over previous
#include <cuda_runtime.h>
#include <cuda_fp16.h>
#include <math.h>
#include <stdint.h>
#include <mma.h>

using namespace nvcuda;

#define B_  2
#define T_  2048
#define E_  1024
#define H_  16
#define HS_ 64
#define NROWS (B_*T_)   // 4096 rows
#define FF  (4*E_)      // 4096

// ---------------- scratch ----------------------------------------------------
__device__ __half g_h16  [NROWS * E_];      // LN1 output (fp16)
__device__ __half g_wqkv16[E_ * 3 * E_];    // repacked QKV weights [E,3E] fp16
__device__ __half g_wp16 [E_ * E_];
__device__ __half g_w116 [E_ * FF];
__device__ __half g_w216 [FF * E_];
__device__ __half g_qkv16[NROWS * 3 * E_];  // Q|K|V fp16
__device__ __half g_attn16[NROWS * E_];     // attention out fp16
__device__ float  g_x1   [NROWS * E_];      // residual 1 (fp32)
__device__ __half g_h2_16[NROWS * E_];      // LN2 output fp16
__device__ __half g_ff116[NROWS * FF];      // FFN hidden fp16

__device__ __forceinline__ void cp_async16(uint32_t dst, const void* src) {
    asm volatile("cp.async.cg.shared.global [%0], [%1], 16;" :: "r"(dst), "l"(src));
}
__device__ __forceinline__ uint32_t smem_u32(const void* p) {
    uint32_t a;
    asm("{ .reg .u64 t; cvta.to.shared.u64 t, %1; cvt.u32.u64 %0, t; }" : "=r"(a) : "l"(p));
    return a;
}
// D += A*B, m16n8k16 fp16 inputs, fp32 accum
__device__ __forceinline__ void mma16(float* c, const uint32_t* a, uint32_t b0, uint32_t b1) {
    asm volatile("mma.sync.aligned.m16n8k16.row.col.f32.f16.f16.f32 "
        "{%0,%1,%2,%3}, {%4,%5,%6,%7}, {%8,%9}, {%0,%1,%2,%3};"
        : "+f"(c[0]), "+f"(c[1]), "+f"(c[2]), "+f"(c[3])
        : "r"(a[0]), "r"(a[1]), "r"(a[2]), "r"(a[3]), "r"(b0), "r"(b1));
}

// ---------------- LayerNorm (fp32 in -> fp16 out) ----------------------------
__global__ __launch_bounds__(256) void ln_kernel(const float* __restrict__ x,
                                                 const float* __restrict__ g,
                                                 const float* __restrict__ b,
                                                 __half* __restrict__ out)
{
    int row = blockIdx.x;
    int tid = threadIdx.x;
    const float4* xr = reinterpret_cast<const float4*>(x + (size_t)row * E_);
    float4 v = xr[tid];
    float s  = v.x + v.y + v.z + v.w;
    float sq = v.x*v.x + v.y*v.y + v.z*v.z + v.w*v.w;

    __shared__ float sh[16];
    __shared__ float s_mu, s_rs;
    #pragma unroll
    for (int o = 16; o > 0; o >>= 1) {
        s  += __shfl_down_sync(0xffffffffu, s,  o);
        sq += __shfl_down_sync(0xffffffffu, sq, o);
    }
    int lane = tid & 31, wid = tid >> 5;
    if (lane == 0) { sh[wid] = s; sh[8 + wid] = sq; }
    __syncthreads();
    if (tid == 0) {
        float ts = 0.f, tq = 0.f;
        #pragma unroll
        for (int w = 0; w < 8; w++) { ts += sh[w]; tq += sh[8 + w]; }
        float mu  = ts * (1.0f / E_);
        float var = tq * (1.0f / E_) - mu * mu;
        s_mu = mu;
        s_rs = rsqrtf(var + 1e-5f);
    }
    __syncthreads();
    float mu = s_mu, rs = s_rs;
    float4 gg = reinterpret_cast<const float4*>(g)[tid];
    float4 bb = reinterpret_cast<const float4*>(b)[tid];
    __half2 h0 = __floats2half2_rn((v.x - mu) * rs * gg.x + bb.x,
                                   (v.y - mu) * rs * gg.y + bb.y);
    __half2 h1 = __floats2half2_rn((v.z - mu) * rs * gg.z + bb.z,
                                   (v.w - mu) * rs * gg.w + bb.w);
    __half2* op = reinterpret_cast<__half2*>(out + (size_t)row * E_ + tid * 4);
    op[0] = h0; op[1] = h1;
}

// ---------------- fp32 -> fp16 convert (vectorized, 8/thread) ----------------
__global__ void f2h_kernel(const float* __restrict__ in, __half* __restrict__ out, int n8)
{
    int i = blockIdx.x * blockDim.x + threadIdx.x;
    if (i >= n8) return;
    const float4* ip = reinterpret_cast<const float4*>(in) + 2 * (size_t)i;
    float4 a = ip[0], b = ip[1];
    __half2 h[4] = { __floats2half2_rn(a.x, a.y), __floats2half2_rn(a.z, a.w),
                     __floats2half2_rn(b.x, b.y), __floats2half2_rn(b.z, b.w) };
    *reinterpret_cast<float4*>(out + 8 * (size_t)i) = *reinterpret_cast<float4*>(h);
}

// ---------------- Repack Wq/Wk/Wv [H,E,HS] -> [E, 3E] fp16 (4/thread) --------
__global__ void repack_kernel(const float* __restrict__ Wq,
                              const float* __restrict__ Wk,
                              const float* __restrict__ Wv,
                              __half* __restrict__ Wqkv)
{
    int i = blockIdx.x * blockDim.x + threadIdx.x;   // over H*E*HS/4
    if (i >= H_ * E_ * HS_ / 4) return;
    int h = i / (E_ * HS_ / 4);
    int r = i % (E_ * HS_ / 4);
    int e = r / (HS_ / 4);
    int d4 = (r % (HS_ / 4)) * 4;
    int col = h * HS_ + d4;
    size_t base = (size_t)e * (3 * E_);
    size_t src = (size_t)i * 4;
    float4 q = *reinterpret_cast<const float4*>(Wq + src);
    float4 k = *reinterpret_cast<const float4*>(Wk + src);
    float4 v = *reinterpret_cast<const float4*>(Wv + src);
    __half2 qh[2] = { __floats2half2_rn(q.x, q.y), __floats2half2_rn(q.z, q.w) };
    __half2 kh[2] = { __floats2half2_rn(k.x, k.y), __floats2half2_rn(k.z, k.w) };
    __half2 vh[2] = { __floats2half2_rn(v.x, v.y), __floats2half2_rn(v.z, v.w) };
    *reinterpret_cast<float2*>(Wqkv + base + col)           = *reinterpret_cast<float2*>(qh);
    *reinterpret_cast<float2*>(Wqkv + base + E_ + col)      = *reinterpret_cast<float2*>(kh);
    *reinterpret_cast<float2*>(Wqkv + base + 2 * E_ + col)  = *reinterpret_cast<float2*>(vh);
}

// ---------------- fp16 WMMA GEMM (m16n16k16, fp32 accum) ---------------------
#define BM   128
#define BN   128
#define BKC  32
#define ASTH 40
#define BSTH 136
#define STAGE_H (BM*ASTH + BKC*BSTH)
#define NSTG 3
#define CST  132
#define GSMEM (BM * CST * 4)

__global__ __launch_bounds__(128, 2) void h16_gemm(
    const __half* __restrict__ A, const __half* __restrict__ Bm,
    float* __restrict__ C, __half* __restrict__ Ch, int M, int N, int K,
    const float* __restrict__ bias, const float* __restrict__ res, int relu)
{
    extern __shared__ float sm[];
    __half* smh = reinterpret_cast<__half*>(sm);
    uint32_t smb = smem_u32(sm);

    int tid  = threadIdx.x;
    int wid  = tid >> 5;
    int wm   = wid & 1;
    int wn   = wid >> 1;
    int m0   = blockIdx.y * BM;
    int n0   = blockIdx.x * BN;
    int NC   = K / BKC;

    wmma::fragment<wmma::accumulator, 16, 16, 16, float> acc[4][4];
    #pragma unroll
    for (int i = 0; i < 4; i++)
        #pragma unroll
        for (int j = 0; j < 4; j++)
            wmma::fill_fragment(acc[i][j], 0.0f);

    auto issue = [&](int c) {
        int buf = c % NSTG;
        uint32_t stA = smb + (uint32_t)(buf * STAGE_H) * 2u;
        uint32_t stB = stA + (uint32_t)(BM * ASTH) * 2u;
        int k0 = c * BKC;
        #pragma unroll
        for (int t = 0; t < 4; t++) {
            int idx = tid + t * 128;
            int r  = idx >> 2;
            int kk = (idx & 3) * 8;
            cp_async16(stA + (uint32_t)(r * ASTH + kk) * 2u,
                       A + (size_t)(m0 + r) * K + k0 + kk);
        }
        #pragma unroll
        for (int t = 0; t < 4; t++) {
            int idx = tid + t * 128;
            int r  = idx >> 4;
            int nn = (idx & 15) * 8;
            cp_async16(stB + (uint32_t)(r * BSTH + nn) * 2u,
                       Bm + (size_t)(k0 + r) * N + n0 + nn);
        }
        asm volatile("cp.async.commit_group;" ::: "memory");
    };

    issue(0);
    if (NC > 1) issue(1);

    for (int c = 0; c < NC; c++) {
        if (c + 2 < NC) {
            issue(c + 2);
            asm volatile("cp.async.wait_group 2;" ::: "memory");
        } else if (c + 1 < NC) {
            asm volatile("cp.async.wait_group 1;" ::: "memory");
        } else {
            asm volatile("cp.async.wait_group 0;" ::: "memory");
        }
        __syncthreads();

        const __half* sA = smh + (c % NSTG) * STAGE_H;
        const __half* sB = sA + BM * ASTH;

        #pragma unroll
        for (int kk = 0; kk < 2; kk++) {
            wmma::fragment<wmma::matrix_a, 16, 16, 16, __half, wmma::row_major> af[4];
            wmma::fragment<wmma::matrix_b, 16, 16, 16, __half, wmma::row_major> bf[4];
            #pragma unroll
            for (int i = 0; i < 4; i++)
                wmma::load_matrix_sync(af[i], sA + (wm * 64 + i * 16) * ASTH + kk * 16, ASTH);
            #pragma unroll
            for (int j = 0; j < 4; j++)
                wmma::load_matrix_sync(bf[j], sB + (kk * 16) * BSTH + wn * 64 + j * 16, BSTH);
            #pragma unroll
            for (int i = 0; i < 4; i++)
                #pragma unroll
                for (int j = 0; j < 4; j++)
                    wmma::mma_sync(acc[i][j], af[i], bf[j], acc[i][j]);
        }
        __syncthreads();
    }

    float* Cs = sm;
    #pragma unroll
    for (int i = 0; i < 4; i++)
        #pragma unroll
        for (int j = 0; j < 4; j++)
            wmma::store_matrix_sync(Cs + (wm * 64 + i * 16) * CST + wn * 64 + j * 16,
                                    acc[i][j], CST, wmma::mem_row_major);
    __syncthreads();

    for (int idx = tid; idx < BM * BN / 4; idx += 128) {
        int r  = idx >> 5;
        int c4 = idx & 31;
        float4 v = *reinterpret_cast<const float4*>(Cs + r * CST + c4 * 4);
        int col = n0 + c4 * 4;
        size_t row = (size_t)(m0 + r);
        if (bias) {
            float4 bb = *reinterpret_cast<const float4*>(bias + col);
            v.x += bb.x; v.y += bb.y; v.z += bb.z; v.w += bb.w;
        }
        if (relu) {
            v.x = fmaxf(v.x, 0.f); v.y = fmaxf(v.y, 0.f);
            v.z = fmaxf(v.z, 0.f); v.w = fmaxf(v.w, 0.f);
        }
        if (res) {
            float4 rr = *reinterpret_cast<const float4*>(res + row * N + col);
            v.x += rr.x; v.y += rr.y; v.z += rr.z; v.w += rr.w;
        }
        if (Ch) {
            __half2* hp = reinterpret_cast<__half2*>(Ch + row * N + col);
            hp[0] = __floats2half2_rn(v.x, v.y);
            hp[1] = __floats2half2_rn(v.z, v.w);
        } else {
            *reinterpret_cast<float4*>(C + row * N + col) = v;
        }
    }
}

// ---------------- fp16 tensor-core causal flash attention --------------------
// 128 threads = 4 warps; warp w owns q rows [16w,16w+16). mma m16n8k16 fp16.
#define APH 72                                  // smem row pad (halves)
#define ATT_HALVES (5 * 64 * APH)               // K0,K1,V0,V1,P = 46080 B

__global__ __launch_bounds__(128) void attn_kernel(const __half* __restrict__ qkv,
                                                   __half* __restrict__ out)
{
    __shared__ __half asm16[ATT_HALVES];
    uint32_t smu = smem_u32(asm16);
    __half* Sb = asm16 + 4 * 64 * APH;

    int tid = threadIdx.x, w = tid >> 5, lane = tid & 31;
    int gid = lane >> 2, tig = lane & 3;
    int qt = (T_ / 64 - 1) - blockIdx.x;          // heavy blocks first
    int bh = blockIdx.y, b = bh >> 4, h = bh & 15;

    // ---- Q fragments (fp16 packed, scaled by HS^-1/2) ----
    uint32_t qa[4][4];
    {
        const __half2 sc2 = __floats2half2_rn(0.125f, 0.125f);
        #pragma unroll
        for (int ks = 0; ks < 4; ks++)
            #pragma unroll
            for (int r = 0; r < 4; r++) {
                int row = w * 16 + gid + (r & 1) * 8;
                int col = ks * 16 + 2 * tig + ((r >> 1) * 8);
                __half2 v = *reinterpret_cast<const __half2*>(
                    qkv + (size_t)(b * T_ + qt * 64 + row) * (3 * E_) + h * HS_ + col);
                v = __hmul2(v, sc2);
                qa[ks][r] = *reinterpret_cast<uint32_t*>(&v);
            }
    }

    float oa[8][4];
    #pragma unroll
    for (int nt = 0; nt < 8; nt++)
        #pragma unroll
        for (int r = 0; r < 4; r++) oa[nt][r] = 0.f;
    float m0 = -1e30f, m1 = -1e30f, l0 = 0.f, l1 = 0.f;

    // ---- K/V tile loader (double buffered, cp.async; 64 rows x 128B) ----
    auto loadKV = [&](int kt, int bu) {
        const __half* kb = qkv + (size_t)(b * T_ + kt * 64) * (3 * E_) + E_ + h * HS_;
        const __half* vb = kb + E_;
        uint32_t kbase = smu + (uint32_t)(bu * 64 * APH) * 2u;
        uint32_t vbase = smu + (uint32_t)((2 + bu) * 64 * APH) * 2u;
        #pragma unroll
        for (int t = 0; t < 4; t++) {
            int i = tid + t * 128;
            int r = i >> 3, c = (i & 7) * 8;       // halves
            cp_async16(kbase + (uint32_t)(r * APH + c) * 2u, kb + (size_t)r * (3 * E_) + c);
            cp_async16(vbase + (uint32_t)(r * APH + c) * 2u, vb + (size_t)r * (3 * E_) + c);
        }
        asm volatile("cp.async.commit_group;" ::: "memory");
    };

    loadKV(0, 0);

    for (int kt = 0; kt <= qt; kt++) {
        int bu = kt & 1;
        if (kt < qt) {
            loadKV(kt + 1, bu ^ 1);
            asm volatile("cp.async.wait_group 1;" ::: "memory");
        } else {
            asm volatile("cp.async.wait_group 0;" ::: "memory");
        }
        __syncthreads();

        const __half* Ks = asm16 + bu * 64 * APH;
        const __half* Vs = asm16 + (2 + bu) * 64 * APH;

        // ---- S = Q @ K^T ----
        float sa[8][4];
        #pragma unroll
        for (int nt = 0; nt < 8; nt++)
            #pragma unroll
            for (int r = 0; r < 4; r++) sa[nt][r] = 0.f;

        #pragma unroll
        for (int ks = 0; ks < 4; ks++) {
            #pragma unroll
            for (int nt = 0; nt < 8; nt++) {
                const __half* kr = Ks + (nt * 8 + gid) * APH + ks * 16 + 2 * tig;
                uint32_t b0 = *reinterpret_cast<const uint32_t*>(kr);
                uint32_t b1 = *reinterpret_cast<const uint32_t*>(kr + 8);
                mma16(sa[nt], qa[ks], b0, b1);
            }
        }

        // ---- causal mask (diagonal tile only) ----
        if (kt == qt) {
            int r0 = w * 16 + gid, r1 = r0 + 8;
            #pragma unroll
            for (int nt = 0; nt < 8; nt++) {
                int c0 = nt * 8 + 2 * tig, c1 = c0 + 1;
                if (c0 > r0) sa[nt][0] = -1e30f;
                if (c1 > r0) sa[nt][1] = -1e30f;
                if (c0 > r1) sa[nt][2] = -1e30f;
                if (c1 > r1) sa[nt][3] = -1e30f;
            }
        }

        // ---- online softmax ----
        float mt0 = -1e30f, mt1 = -1e30f;
        #pragma unroll
        for (int nt = 0; nt < 8; nt++) {
            mt0 = fmaxf(mt0, fmaxf(sa[nt][0], sa[nt][1]));
            mt1 = fmaxf(mt1, fmaxf(sa[nt][2], sa[nt][3]));
        }
        mt0 = fmaxf(mt0, __shfl_xor_sync(0xffffffffu, mt0, 1));
        mt0 = fmaxf(mt0, __shfl_xor_sync(0xffffffffu, mt0, 2));
        mt1 = fmaxf(mt1, __shfl_xor_sync(0xffffffffu, mt1, 1));
        mt1 = fmaxf(mt1, __shfl_xor_sync(0xffffffffu, mt1, 2));

        float mn0 = fmaxf(m0, mt0), mn1 = fmaxf(m1, mt1);
        float cr0 = __expf(m0 - mn0), cr1 = __expf(m1 - mn1);
        m0 = mn0; m1 = mn1;

        float s0 = 0.f, s1 = 0.f;
        __half* Pr0 = Sb + (w * 16 + gid) * APH;
        __half* Pr1 = Pr0 + 8 * APH;
        #pragma unroll
        for (int nt = 0; nt < 8; nt++) {
            __half2 hp0 = __floats2half2_rn(__expf(sa[nt][0] - mn0), __expf(sa[nt][1] - mn0));
            __half2 hp1 = __floats2half2_rn(__expf(sa[nt][2] - mn1), __expf(sa[nt][3] - mn1));
            float2 f0 = __half22float2(hp0), f1 = __half22float2(hp1);
            s0 += f0.x + f0.y;  s1 += f1.x + f1.y;
            *reinterpret_cast<__half2*>(Pr0 + nt * 8 + 2 * tig) = hp0;
            *reinterpret_cast<__half2*>(Pr1 + nt * 8 + 2 * tig) = hp1;
        }
        s0 += __shfl_xor_sync(0xffffffffu, s0, 1);
        s0 += __shfl_xor_sync(0xffffffffu, s0, 2);
        s1 += __shfl_xor_sync(0xffffffffu, s1, 1);
        s1 += __shfl_xor_sync(0xffffffffu, s1, 2);
        l0 = l0 * cr0 + s0;
        l1 = l1 * cr1 + s1;

        #pragma unroll
        for (int nt = 0; nt < 8; nt++) {
            oa[nt][0] *= cr0; oa[nt][1] *= cr0;
            oa[nt][2] *= cr1; oa[nt][3] *= cr1;
        }
        __syncwarp();

        // ---- O += P @ V ----
        #pragma unroll
        for (int ks = 0; ks < 4; ks++) {
            uint32_t pa[4];
            const __half* p0 = Sb + (w * 16 + gid) * APH + ks * 16 + 2 * tig;
            const __half* p1 = p0 + 8 * APH;
            pa[0] = *reinterpret_cast<const uint32_t*>(p0);
            pa[1] = *reinterpret_cast<const uint32_t*>(p1);
            pa[2] = *reinterpret_cast<const uint32_t*>(p0 + 8);
            pa[3] = *reinterpret_cast<const uint32_t*>(p1 + 8);
            int k0 = ks * 16 + 2 * tig;
            #pragma unroll
            for (int nt = 0; nt < 8; nt++) {
                int n = nt * 8 + gid;
                uint32_t b0 = (uint32_t)__half_as_ushort(Vs[(k0 + 0) * APH + n]) |
                              ((uint32_t)__half_as_ushort(Vs[(k0 + 1) * APH + n]) << 16);
                uint32_t b1 = (uint32_t)__half_as_ushort(Vs[(k0 + 8) * APH + n]) |
                              ((uint32_t)__half_as_ushort(Vs[(k0 + 9) * APH + n]) << 16);
                mma16(oa[nt], pa, b0, b1);
            }
        }
        __syncthreads();
    }

    // ---- finalize ----
    float i0 = 1.f / l0, i1 = 1.f / l1;
    int r0 = qt * 64 + w * 16 + gid;
    #pragma unroll
    for (int nt = 0; nt < 8; nt++) {
        int col = h * HS_ + nt * 8 + 2 * tig;
        __half2* p0 = reinterpret_cast<__half2*>(out + (size_t)(b * T_ + r0) * E_ + col);
        __half2* p1 = reinterpret_cast<__half2*>(out + (size_t)(b * T_ + r0 + 8) * E_ + col);
        *p0 = __floats2half2_rn(oa[nt][0] * i0, oa[nt][1] * i0);
        *p1 = __floats2half2_rn(oa[nt][2] * i1, oa[nt][3] * i1);
    }
}

// ---------------- host -------------------------------------------------------
extern "C" void kernel_launch(void* const* d_in, const int* in_sizes, int n_in,
                              void* d_out, int out_size)
{
    const float* x   = (const float*)d_in[0];
    const float* Wq  = (const float*)d_in[1];
    const float* Wk  = (const float*)d_in[2];
    const float* Wv  = (const float*)d_in[3];
    const float* Wp  = (const float*)d_in[4];
    const float* bp  = (const float*)d_in[5];
    const float* W1  = (const float*)d_in[6];
    const float* b1  = (const float*)d_in[7];
    const float* W2  = (const float*)d_in[8];
    const float* b2  = (const float*)d_in[9];
    const float* g1  = (const float*)d_in[10];
    const float* be1 = (const float*)d_in[11];
    const float* g2  = (const float*)d_in[12];
    const float* be2 = (const float*)d_in[13];
    float* out = (float*)d_out;

    __half *h16, *wqkv16, *wp16, *w116, *w216, *qkv16, *attn16, *h2_16, *ff116;
    float *x1;
    cudaGetSymbolAddress((void**)&h16,    g_h16);
    cudaGetSymbolAddress((void**)&wqkv16, g_wqkv16);
    cudaGetSymbolAddress((void**)&wp16,   g_wp16);
    cudaGetSymbolAddress((void**)&w116,   g_w116);
    cudaGetSymbolAddress((void**)&w216,   g_w216);
    cudaGetSymbolAddress((void**)&qkv16,  g_qkv16);
    cudaGetSymbolAddress((void**)&attn16, g_attn16);
    cudaGetSymbolAddress((void**)&x1,     g_x1);
    cudaGetSymbolAddress((void**)&h2_16,  g_h2_16);
    cudaGetSymbolAddress((void**)&ff116,  g_ff116);

    cudaFuncSetAttribute(h16_gemm, cudaFuncAttributeMaxDynamicSharedMemorySize, GSMEM);

    // prep: LN1, weight converts (vectorized)
    ln_kernel<<<NROWS, 256>>>(x, g1, be1, h16);
    repack_kernel<<<(H_ * E_ * HS_ / 4 + 255) / 256, 256>>>(Wq, Wk, Wv, wqkv16);
    f2h_kernel<<<(E_ * E_ / 8 + 255) / 256, 256>>>(Wp, wp16, E_ * E_ / 8);
    f2h_kernel<<<(E_ * FF / 8 + 255) / 256, 256>>>(W1, w116, E_ * FF / 8);
    f2h_kernel<<<(FF * E_ / 8 + 255) / 256, 256>>>(W2, w216, FF * E_ / 8);

    // QKV = h @ Wqkv -> fp16
    h16_gemm<<<dim3(3*E_/BN, NROWS/BM), 128, GSMEM>>>(
        h16, wqkv16, nullptr, qkv16, NROWS, 3*E_, E_, nullptr, nullptr, 0);
    // attention (fp16 tensor cores) -> fp16
    attn_kernel<<<dim3(T_/64, B_*H_), 128>>>(qkv16, attn16);
    // x1 = x + attn @ Wp + bp  (fp32 out)
    h16_gemm<<<dim3(E_/BN, NROWS/BM), 128, GSMEM>>>(
        attn16, wp16, x1, nullptr, NROWS, E_, E_, bp, x, 0);
    // h2 = LN2(x1) -> fp16
    ln_kernel<<<NROWS, 256>>>(x1, g2, be2, h2_16);
    // ff1 = relu(h2 @ W1 + b1) -> fp16
    h16_gemm<<<dim3(FF/BN, NROWS/BM), 128, GSMEM>>>(
        h2_16, w116, nullptr, ff116, NROWS, FF, E_, b1, nullptr, 1);
    // out = x1 + ff1 @ W2 + b2  (fp32 out, K = 4096)
    h16_gemm<<<dim3(E_/BN, NROWS/BM), 128, GSMEM>>>(
        ff116, w216, out, nullptr, NROWS, E_, FF, b2, x1, 0);
}

// round 11
// speedup vs baseline: 8.5742x; 1.0905x over previous
#include <cuda_runtime.h>
#include <cuda_fp16.h>
#include <math.h>
#include <stdint.h>
#include <mma.h>

using namespace nvcuda;

#define B_  2
#define T_  2048
#define E_  1024
#define H_  16
#define HS_ 64
#define NROWS (B_*T_)   // 4096 rows
#define FF  (4*E_)      // 4096

// ---------------- scratch ----------------------------------------------------
__device__ __half g_h16  [NROWS * E_];      // LN1 output (fp16)
__device__ __half g_wqkv16[E_ * 3 * E_];    // repacked QKV weights [E,3E] fp16
__device__ __half g_wp16 [E_ * E_];
__device__ __half g_w116 [E_ * FF];
__device__ __half g_w216 [FF * E_];
__device__ __half g_qkv16[NROWS * 3 * E_];  // Q|K|V fp16
__device__ __half g_attn16[NROWS * E_];     // attention out fp16
__device__ float  g_x1   [NROWS * E_];      // residual 1 (fp32)
__device__ __half g_h2_16[NROWS * E_];      // LN2 output fp16
__device__ __half g_ff116[NROWS * FF];      // FFN hidden fp16

__device__ __forceinline__ void cp_async16(uint32_t dst, const void* src) {
    asm volatile("cp.async.cg.shared.global [%0], [%1], 16;" :: "r"(dst), "l"(src));
}
__device__ __forceinline__ uint32_t smem_u32(const void* p) {
    uint32_t a;
    asm("{ .reg .u64 t; cvta.to.shared.u64 t, %1; cvt.u32.u64 %0, t; }" : "=r"(a) : "l"(p));
    return a;
}
// D += A*B, m16n8k16 fp16 inputs, fp32 accum
__device__ __forceinline__ void mma16(float* c, const uint32_t* a, uint32_t b0, uint32_t b1) {
    asm volatile("mma.sync.aligned.m16n8k16.row.col.f32.f16.f16.f32 "
        "{%0,%1,%2,%3}, {%4,%5,%6,%7}, {%8,%9}, {%0,%1,%2,%3};"
        : "+f"(c[0]), "+f"(c[1]), "+f"(c[2]), "+f"(c[3])
        : "r"(a[0]), "r"(a[1]), "r"(a[2]), "r"(a[3]), "r"(b0), "r"(b1));
}
__device__ __forceinline__ void ldsm4(uint32_t* r, uint32_t a) {
    asm volatile("ldmatrix.sync.aligned.m8n8.x4.shared.b16 {%0,%1,%2,%3}, [%4];"
        : "=r"(r[0]), "=r"(r[1]), "=r"(r[2]), "=r"(r[3]) : "r"(a));
}
__device__ __forceinline__ void ldsm4t(uint32_t* r, uint32_t a) {
    asm volatile("ldmatrix.sync.aligned.m8n8.x4.trans.shared.b16 {%0,%1,%2,%3}, [%4];"
        : "=r"(r[0]), "=r"(r[1]), "=r"(r[2]), "=r"(r[3]) : "r"(a));
}

// ---------------- LayerNorm (fp32 in -> fp16 out) ----------------------------
__global__ __launch_bounds__(256) void ln_kernel(const float* __restrict__ x,
                                                 const float* __restrict__ g,
                                                 const float* __restrict__ b,
                                                 __half* __restrict__ out)
{
    int row = blockIdx.x;
    int tid = threadIdx.x;
    const float4* xr = reinterpret_cast<const float4*>(x + (size_t)row * E_);
    float4 v = xr[tid];
    float s  = v.x + v.y + v.z + v.w;
    float sq = v.x*v.x + v.y*v.y + v.z*v.z + v.w*v.w;

    __shared__ float sh[16];
    __shared__ float s_mu, s_rs;
    #pragma unroll
    for (int o = 16; o > 0; o >>= 1) {
        s  += __shfl_down_sync(0xffffffffu, s,  o);
        sq += __shfl_down_sync(0xffffffffu, sq, o);
    }
    int lane = tid & 31, wid = tid >> 5;
    if (lane == 0) { sh[wid] = s; sh[8 + wid] = sq; }
    __syncthreads();
    if (tid == 0) {
        float ts = 0.f, tq = 0.f;
        #pragma unroll
        for (int w = 0; w < 8; w++) { ts += sh[w]; tq += sh[8 + w]; }
        float mu  = ts * (1.0f / E_);
        float var = tq * (1.0f / E_) - mu * mu;
        s_mu = mu;
        s_rs = rsqrtf(var + 1e-5f);
    }
    __syncthreads();
    float mu = s_mu, rs = s_rs;
    float4 gg = reinterpret_cast<const float4*>(g)[tid];
    float4 bb = reinterpret_cast<const float4*>(b)[tid];
    __half2 h0 = __floats2half2_rn((v.x - mu) * rs * gg.x + bb.x,
                                   (v.y - mu) * rs * gg.y + bb.y);
    __half2 h1 = __floats2half2_rn((v.z - mu) * rs * gg.z + bb.z,
                                   (v.w - mu) * rs * gg.w + bb.w);
    __half2* op = reinterpret_cast<__half2*>(out + (size_t)row * E_ + tid * 4);
    op[0] = h0; op[1] = h1;
}

// ---------------- fused fp32 -> fp16 convert for 3 weights -------------------
__device__ __forceinline__ void cvt8(const float* ip, __half* op) {
    const float4* p = reinterpret_cast<const float4*>(ip);
    float4 a = p[0], b = p[1];
    __half2 h[4] = { __floats2half2_rn(a.x, a.y), __floats2half2_rn(a.z, a.w),
                     __floats2half2_rn(b.x, b.y), __floats2half2_rn(b.z, b.w) };
    *reinterpret_cast<float4*>(op) = *reinterpret_cast<float4*>(h);
}
__global__ void f2h3_kernel(const float* __restrict__ a, __half* __restrict__ oa,
                            const float* __restrict__ b, __half* __restrict__ ob,
                            const float* __restrict__ c, __half* __restrict__ oc,
                            int na8, int nb8, int nc8)
{
    int i = blockIdx.x * blockDim.x + threadIdx.x;
    if (i < na8)                 { cvt8(a + 8 * (size_t)i, oa + 8 * (size_t)i); return; }
    i -= na8;
    if (i < nb8)                 { cvt8(b + 8 * (size_t)i, ob + 8 * (size_t)i); return; }
    i -= nb8;
    if (i < nc8)                 { cvt8(c + 8 * (size_t)i, oc + 8 * (size_t)i); }
}

// ---------------- Repack Wq/Wk/Wv [H,E,HS] -> [E, 3E] fp16 (4/thread) --------
__global__ void repack_kernel(const float* __restrict__ Wq,
                              const float* __restrict__ Wk,
                              const float* __restrict__ Wv,
                              __half* __restrict__ Wqkv)
{
    int i = blockIdx.x * blockDim.x + threadIdx.x;   // over H*E*HS/4
    if (i >= H_ * E_ * HS_ / 4) return;
    int h = i / (E_ * HS_ / 4);
    int r = i % (E_ * HS_ / 4);
    int e = r / (HS_ / 4);
    int d4 = (r % (HS_ / 4)) * 4;
    int col = h * HS_ + d4;
    size_t base = (size_t)e * (3 * E_);
    size_t src = (size_t)i * 4;
    float4 q = *reinterpret_cast<const float4*>(Wq + src);
    float4 k = *reinterpret_cast<const float4*>(Wk + src);
    float4 v = *reinterpret_cast<const float4*>(Wv + src);
    __half2 qh[2] = { __floats2half2_rn(q.x, q.y), __floats2half2_rn(q.z, q.w) };
    __half2 kh[2] = { __floats2half2_rn(k.x, k.y), __floats2half2_rn(k.z, k.w) };
    __half2 vh[2] = { __floats2half2_rn(v.x, v.y), __floats2half2_rn(v.z, v.w) };
    *reinterpret_cast<float2*>(Wqkv + base + col)           = *reinterpret_cast<float2*>(qh);
    *reinterpret_cast<float2*>(Wqkv + base + E_ + col)      = *reinterpret_cast<float2*>(kh);
    *reinterpret_cast<float2*>(Wqkv + base + 2 * E_ + col)  = *reinterpret_cast<float2*>(vh);
}

// ---------------- fp16 WMMA GEMM (m16n16k16, fp32 accum, BK=64) --------------
#define BM   128
#define BN   128
#define BKC  64
#define ASTH 72                       // A row stride (halves): 144B = 9x16B, odd -> conflict-free
#define BSTH 136                      // B row stride (halves): 272B = 17x16B, odd
#define STAGE_H (BM*ASTH + BKC*BSTH)  // 9216 + 8704 = 17920 halves / stage
#define NSTG 3
#define CST  132
#define GSMEM (NSTG * STAGE_H * 2)    // 107520 B  (> 128*132*4 = 67584 staging)

__global__ __launch_bounds__(128, 2) void h16_gemm(
    const __half* __restrict__ A, const __half* __restrict__ Bm,
    float* __restrict__ C, __half* __restrict__ Ch, int M, int N, int K,
    const float* __restrict__ bias, const float* __restrict__ res, int relu)
{
    extern __shared__ float sm[];
    __half* smh = reinterpret_cast<__half*>(sm);
    uint32_t smb = smem_u32(sm);

    int tid  = threadIdx.x;
    int wid  = tid >> 5;
    int wm   = wid & 1;
    int wn   = wid >> 1;
    int m0   = blockIdx.y * BM;
    int n0   = blockIdx.x * BN;
    int NC   = K / BKC;

    wmma::fragment<wmma::accumulator, 16, 16, 16, float> acc[4][4];
    #pragma unroll
    for (int i = 0; i < 4; i++)
        #pragma unroll
        for (int j = 0; j < 4; j++)
            wmma::fill_fragment(acc[i][j], 0.0f);

    // per stage: A 128x64h (1024 x16B) + B 64x128h (1024 x16B); 16 cp/thread
    auto issue = [&](int c) {
        int buf = c % NSTG;
        uint32_t stA = smb + (uint32_t)(buf * STAGE_H) * 2u;
        uint32_t stB = stA + (uint32_t)(BM * ASTH) * 2u;
        int k0 = c * BKC;
        #pragma unroll
        for (int t = 0; t < 8; t++) {
            int idx = tid + t * 128;
            int r  = idx >> 3;            // 0..127
            int kk = (idx & 7) * 8;       // halves 0..56
            cp_async16(stA + (uint32_t)(r * ASTH + kk) * 2u,
                       A + (size_t)(m0 + r) * K + k0 + kk);
        }
        #pragma unroll
        for (int t = 0; t < 8; t++) {
            int idx = tid + t * 128;
            int r  = idx >> 4;            // 0..63
            int nn = (idx & 15) * 8;      // halves 0..120
            cp_async16(stB + (uint32_t)(r * BSTH + nn) * 2u,
                       Bm + (size_t)(k0 + r) * N + n0 + nn);
        }
        asm volatile("cp.async.commit_group;" ::: "memory");
    };

    issue(0);
    if (NC > 1) issue(1);

    for (int c = 0; c < NC; c++) {
        if (c + 2 < NC) {
            issue(c + 2);
            asm volatile("cp.async.wait_group 2;" ::: "memory");
        } else if (c + 1 < NC) {
            asm volatile("cp.async.wait_group 1;" ::: "memory");
        } else {
            asm volatile("cp.async.wait_group 0;" ::: "memory");
        }
        __syncthreads();

        const __half* sA = smh + (c % NSTG) * STAGE_H;
        const __half* sB = sA + BM * ASTH;

        #pragma unroll
        for (int kk = 0; kk < 4; kk++) {
            wmma::fragment<wmma::matrix_a, 16, 16, 16, __half, wmma::row_major> af[4];
            wmma::fragment<wmma::matrix_b, 16, 16, 16, __half, wmma::row_major> bf[4];
            #pragma unroll
            for (int i = 0; i < 4; i++)
                wmma::load_matrix_sync(af[i], sA + (wm * 64 + i * 16) * ASTH + kk * 16, ASTH);
            #pragma unroll
            for (int j = 0; j < 4; j++)
                wmma::load_matrix_sync(bf[j], sB + (kk * 16) * BSTH + wn * 64 + j * 16, BSTH);
            #pragma unroll
            for (int i = 0; i < 4; i++)
                #pragma unroll
                for (int j = 0; j < 4; j++)
                    wmma::mma_sync(acc[i][j], af[i], bf[j], acc[i][j]);
        }
        __syncthreads();
    }

    float* Cs = sm;
    #pragma unroll
    for (int i = 0; i < 4; i++)
        #pragma unroll
        for (int j = 0; j < 4; j++)
            wmma::store_matrix_sync(Cs + (wm * 64 + i * 16) * CST + wn * 64 + j * 16,
                                    acc[i][j], CST, wmma::mem_row_major);
    __syncthreads();

    for (int idx = tid; idx < BM * BN / 4; idx += 128) {
        int r  = idx >> 5;
        int c4 = idx & 31;
        float4 v = *reinterpret_cast<const float4*>(Cs + r * CST + c4 * 4);
        int col = n0 + c4 * 4;
        size_t row = (size_t)(m0 + r);
        if (bias) {
            float4 bb = *reinterpret_cast<const float4*>(bias + col);
            v.x += bb.x; v.y += bb.y; v.z += bb.z; v.w += bb.w;
        }
        if (relu) {
            v.x = fmaxf(v.x, 0.f); v.y = fmaxf(v.y, 0.f);
            v.z = fmaxf(v.z, 0.f); v.w = fmaxf(v.w, 0.f);
        }
        if (res) {
            float4 rr = *reinterpret_cast<const float4*>(res + row * N + col);
            v.x += rr.x; v.y += rr.y; v.z += rr.z; v.w += rr.w;
        }
        if (Ch) {
            __half2* hp = reinterpret_cast<__half2*>(Ch + row * N + col);
            hp[0] = __floats2half2_rn(v.x, v.y);
            hp[1] = __floats2half2_rn(v.z, v.w);
        } else {
            *reinterpret_cast<float4*>(C + row * N + col) = v;
        }
    }
}

// ---------------- fp16 tensor-core causal flash attention --------------------
// 128 threads = 4 warps; warp w owns q rows [16w,16w+16).
// P lives in registers (S-accum layout == A-frag layout); K/V via ldmatrix.
#define APH 72                                  // row pad (halves): 144B, odd x16B

__global__ __launch_bounds__(128) void attn_kernel(const __half* __restrict__ qkv,
                                                   __half* __restrict__ out)
{
    __shared__ __half asm16[4 * 64 * APH];      // K0,K1,V0,V1 = 36864 B
    uint32_t smu = smem_u32(asm16);

    int tid = threadIdx.x, w = tid >> 5, lane = tid & 31;
    int gid = lane >> 2, tig = lane & 3;
    int g8  = lane >> 3, i8 = lane & 7;         // ldmatrix address groups
    int qt = (T_ / 64 - 1) - blockIdx.x;        // heavy blocks first
    int bh = blockIdx.y, b = bh >> 4, h = bh & 15;

    // ldmatrix per-thread address components
    int rowK = ((g8 >> 1) << 3) + i8;           // + ntp*16 ; col + ks*16 + (g8&1)*8
    int colK = (g8 & 1) << 3;
    int rowV = ((g8 & 1) << 3) + i8;            // + ks*16 ; col + ntp*16 + (g8>>1)*8
    int colV = (g8 >> 1) << 3;

    // ---- Q fragments (fp16 packed, scaled) ----
    uint32_t qa[4][4];
    {
        const __half2 sc2 = __floats2half2_rn(0.125f, 0.125f);
        #pragma unroll
        for (int ks = 0; ks < 4; ks++)
            #pragma unroll
            for (int r = 0; r < 4; r++) {
                int row = w * 16 + gid + (r & 1) * 8;
                int col = ks * 16 + 2 * tig + ((r >> 1) * 8);
                __half2 v = *reinterpret_cast<const __half2*>(
                    qkv + (size_t)(b * T_ + qt * 64 + row) * (3 * E_) + h * HS_ + col);
                v = __hmul2(v, sc2);
                qa[ks][r] = *reinterpret_cast<uint32_t*>(&v);
            }
    }

    float oa[8][4];
    #pragma unroll
    for (int nt = 0; nt < 8; nt++)
        #pragma unroll
        for (int r = 0; r < 4; r++) oa[nt][r] = 0.f;
    float m0 = -1e30f, m1 = -1e30f, l0 = 0.f, l1 = 0.f;

    auto loadKV = [&](int kt, int bu) {
        const __half* kb = qkv + (size_t)(b * T_ + kt * 64) * (3 * E_) + E_ + h * HS_;
        const __half* vb = kb + E_;
        uint32_t kbase = smu + (uint32_t)(bu * 64 * APH) * 2u;
        uint32_t vbase = smu + (uint32_t)((2 + bu) * 64 * APH) * 2u;
        #pragma unroll
        for (int t = 0; t < 4; t++) {
            int i = tid + t * 128;
            int r = i >> 3, c = (i & 7) * 8;
            cp_async16(kbase + (uint32_t)(r * APH + c) * 2u, kb + (size_t)r * (3 * E_) + c);
            cp_async16(vbase + (uint32_t)(r * APH + c) * 2u, vb + (size_t)r * (3 * E_) + c);
        }
        asm volatile("cp.async.commit_group;" ::: "memory");
    };

    loadKV(0, 0);

    for (int kt = 0; kt <= qt; kt++) {
        int bu = kt & 1;
        if (kt < qt) {
            loadKV(kt + 1, bu ^ 1);
            asm volatile("cp.async.wait_group 1;" ::: "memory");
        } else {
            asm volatile("cp.async.wait_group 0;" ::: "memory");
        }
        __syncthreads();

        uint32_t kbase = smu + (uint32_t)(bu * 64 * APH) * 2u;
        uint32_t vbase = smu + (uint32_t)((2 + bu) * 64 * APH) * 2u;

        // ---- S = Q @ K^T  (K B-frags via ldmatrix.x4) ----
        float sa[8][4];
        #pragma unroll
        for (int nt = 0; nt < 8; nt++)
            #pragma unroll
            for (int r = 0; r < 4; r++) sa[nt][r] = 0.f;

        #pragma unroll
        for (int ks = 0; ks < 4; ks++) {
            #pragma unroll
            for (int ntp = 0; ntp < 4; ntp++) {
                uint32_t kf[4];
                ldsm4(kf, kbase + (uint32_t)((ntp * 16 + rowK) * APH + ks * 16 + colK) * 2u);
                mma16(sa[2 * ntp],     qa[ks], kf[0], kf[1]);
                mma16(sa[2 * ntp + 1], qa[ks], kf[2], kf[3]);
            }
        }

        // ---- causal mask (diagonal tile only) ----
        if (kt == qt) {
            int r0 = w * 16 + gid, r1 = r0 + 8;
            #pragma unroll
            for (int nt = 0; nt < 8; nt++) {
                int c0 = nt * 8 + 2 * tig, c1 = c0 + 1;
                if (c0 > r0) sa[nt][0] = -1e30f;
                if (c1 > r0) sa[nt][1] = -1e30f;
                if (c0 > r1) sa[nt][2] = -1e30f;
                if (c1 > r1) sa[nt][3] = -1e30f;
            }
        }

        // ---- online softmax; P packed straight into A-frag registers ----
        float mt0 = -1e30f, mt1 = -1e30f;
        #pragma unroll
        for (int nt = 0; nt < 8; nt++) {
            mt0 = fmaxf(mt0, fmaxf(sa[nt][0], sa[nt][1]));
            mt1 = fmaxf(mt1, fmaxf(sa[nt][2], sa[nt][3]));
        }
        mt0 = fmaxf(mt0, __shfl_xor_sync(0xffffffffu, mt0, 1));
        mt0 = fmaxf(mt0, __shfl_xor_sync(0xffffffffu, mt0, 2));
        mt1 = fmaxf(mt1, __shfl_xor_sync(0xffffffffu, mt1, 1));
        mt1 = fmaxf(mt1, __shfl_xor_sync(0xffffffffu, mt1, 2));

        float mn0 = fmaxf(m0, mt0), mn1 = fmaxf(m1, mt1);
        float cr0 = __expf(m0 - mn0), cr1 = __expf(m1 - mn1);
        m0 = mn0; m1 = mn1;

        float s0 = 0.f, s1 = 0.f;
        uint32_t ph0[8], ph1[8];
        #pragma unroll
        for (int nt = 0; nt < 8; nt++) {
            float e0 = __expf(sa[nt][0] - mn0), e1 = __expf(sa[nt][1] - mn0);
            float e2 = __expf(sa[nt][2] - mn1), e3 = __expf(sa[nt][3] - mn1);
            s0 += e0 + e1;  s1 += e2 + e3;
            __half2 hp0 = __floats2half2_rn(e0, e1);
            __half2 hp1 = __floats2half2_rn(e2, e3);
            ph0[nt] = *reinterpret_cast<uint32_t*>(&hp0);
            ph1[nt] = *reinterpret_cast<uint32_t*>(&hp1);
        }
        s0 += __shfl_xor_sync(0xffffffffu, s0, 1);
        s0 += __shfl_xor_sync(0xffffffffu, s0, 2);
        s1 += __shfl_xor_sync(0xffffffffu, s1, 1);
        s1 += __shfl_xor_sync(0xffffffffu, s1, 2);
        l0 = l0 * cr0 + s0;
        l1 = l1 * cr1 + s1;

        #pragma unroll
        for (int nt = 0; nt < 8; nt++) {
            oa[nt][0] *= cr0; oa[nt][1] *= cr0;
            oa[nt][2] *= cr1; oa[nt][3] *= cr1;
        }

        // ---- O += P @ V  (V B-frags via ldmatrix.x4.trans) ----
        #pragma unroll
        for (int ks = 0; ks < 4; ks++) {
            uint32_t pa[4] = { ph0[2 * ks], ph1[2 * ks], ph0[2 * ks + 1], ph1[2 * ks + 1] };
            #pragma unroll
            for (int ntp = 0; ntp < 4; ntp++) {
                uint32_t vf[4];
                ldsm4t(vf, vbase + (uint32_t)((ks * 16 + rowV) * APH + ntp * 16 + colV) * 2u);
                mma16(oa[2 * ntp],     pa, vf[0], vf[1]);
                mma16(oa[2 * ntp + 1], pa, vf[2], vf[3]);
            }
        }
        __syncthreads();
    }

    // ---- finalize ----
    float i0 = 1.f / l0, i1 = 1.f / l1;
    int r0 = qt * 64 + w * 16 + gid;
    #pragma unroll
    for (int nt = 0; nt < 8; nt++) {
        int col = h * HS_ + nt * 8 + 2 * tig;
        __half2* p0 = reinterpret_cast<__half2*>(out + (size_t)(b * T_ + r0) * E_ + col);
        __half2* p1 = reinterpret_cast<__half2*>(out + (size_t)(b * T_ + r0 + 8) * E_ + col);
        *p0 = __floats2half2_rn(oa[nt][0] * i0, oa[nt][1] * i0);
        *p1 = __floats2half2_rn(oa[nt][2] * i1, oa[nt][3] * i1);
    }
}

// ---------------- host -------------------------------------------------------
extern "C" void kernel_launch(void* const* d_in, const int* in_sizes, int n_in,
                              void* d_out, int out_size)
{
    const float* x   = (const float*)d_in[0];
    const float* Wq  = (const float*)d_in[1];
    const float* Wk  = (const float*)d_in[2];
    const float* Wv  = (const float*)d_in[3];
    const float* Wp  = (const float*)d_in[4];
    const float* bp  = (const float*)d_in[5];
    const float* W1  = (const float*)d_in[6];
    const float* b1  = (const float*)d_in[7];
    const float* W2  = (const float*)d_in[8];
    const float* b2  = (const float*)d_in[9];
    const float* g1  = (const float*)d_in[10];
    const float* be1 = (const float*)d_in[11];
    const float* g2  = (const float*)d_in[12];
    const float* be2 = (const float*)d_in[13];
    float* out = (float*)d_out;

    __half *h16, *wqkv16, *wp16, *w116, *w216, *qkv16, *attn16, *h2_16, *ff116;
    float *x1;
    cudaGetSymbolAddress((void**)&h16,    g_h16);
    cudaGetSymbolAddress((void**)&wqkv16, g_wqkv16);
    cudaGetSymbolAddress((void**)&wp16,   g_wp16);
    cudaGetSymbolAddress((void**)&w116,   g_w116);
    cudaGetSymbolAddress((void**)&w216,   g_w216);
    cudaGetSymbolAddress((void**)&qkv16,  g_qkv16);
    cudaGetSymbolAddress((void**)&attn16, g_attn16);
    cudaGetSymbolAddress((void**)&x1,     g_x1);
    cudaGetSymbolAddress((void**)&h2_16,  g_h2_16);
    cudaGetSymbolAddress((void**)&ff116,  g_ff116);

    cudaFuncSetAttribute(h16_gemm, cudaFuncAttributeMaxDynamicSharedMemorySize, GSMEM);

    // prep: LN1, repack, fused weight converts
    ln_kernel<<<NROWS, 256>>>(x, g1, be1, h16);
    repack_kernel<<<(H_ * E_ * HS_ / 4 + 255) / 256, 256>>>(Wq, Wk, Wv, wqkv16);
    {
        int na8 = E_ * E_ / 8, nb8 = E_ * FF / 8, nc8 = FF * E_ / 8;
        f2h3_kernel<<<(na8 + nb8 + nc8 + 255) / 256, 256>>>(
            Wp, wp16, W1, w116, W2, w216, na8, nb8, nc8);
    }

    // QKV = h @ Wqkv -> fp16
    h16_gemm<<<dim3(3*E_/BN, NROWS/BM), 128, GSMEM>>>(
        h16, wqkv16, nullptr, qkv16, NROWS, 3*E_, E_, nullptr, nullptr, 0);
    // attention (fp16 tensor cores, register-resident P) -> fp16
    attn_kernel<<<dim3(T_/64, B_*H_), 128>>>(qkv16, attn16);
    // x1 = x + attn @ Wp + bp  (fp32 out)
    h16_gemm<<<dim3(E_/BN, NROWS/BM), 128, GSMEM>>>(
        attn16, wp16, x1, nullptr, NROWS, E_, E_, bp, x, 0);
    // h2 = LN2(x1) -> fp16
    ln_kernel<<<NROWS, 256>>>(x1, g2, be2, h2_16);
    // ff1 = relu(h2 @ W1 + b1) -> fp16
    h16_gemm<<<dim3(FF/BN, NROWS/BM), 128, GSMEM>>>(
        h2_16, w116, nullptr, ff116, NROWS, FF, E_, b1, nullptr, 1);
    // out = x1 + ff1 @ W2 + b2  (fp32 out, K = 4096)
    h16_gemm<<<dim3(E_/BN, NROWS/BM), 128, GSMEM>>>(
        ff116, w216, out, nullptr, NROWS, E_, FF, b2, x1, 0);
}